// round 1
// baseline (speedup 1.0000x reference)
#include <cuda_runtime.h>

#define N_ 8
#define C_ 64
#define D_ 16
#define H_ 56
#define W_ 56
#define G_ 8
#define HW_ (H_*W_)
#define DHW_ (D_*HW_)
#define XTOT_ (N_*C_*DHW_)
#define OFFTOT_ (N_*G_*DHW_)
#define CNT_ ((float)(N_*DHW_))

// scratch (device globals: no allocation allowed)
__device__ float g_t1[XTOT_];
__device__ float g_t2[XTOT_];
__device__ float g_off[OFFTOT_];           // fallback if d_out only holds `out`
__device__ float g_sum[4][C_];             // sum1, sqsum1, sum2, sqsum2
__device__ float g_bn[4][C_];              // sc1, sh1, sc2, sh2

__global__ void zero_stats() {
    int t = threadIdx.x;
    if (t < C_) { g_sum[0][t]=0.f; g_sum[1][t]=0.f; g_sum[2][t]=0.f; g_sum[3][t]=0.f; }
}

// ---------------------------------------------------------------------------
// Offset conv: off[n,g,d,h,w] = conv3x3x3(x, w_off) + b_off   (G=8 outputs)
// ---------------------------------------------------------------------------
__global__ __launch_bounds__(256) void offset_conv(
    const float* __restrict__ x, const float* __restrict__ wo,
    const float* __restrict__ bo, float* __restrict__ off)
{
    __shared__ __align__(16) float xs[8][10][34];
    __shared__ __align__(16) float ws[8*9*8];
    const int tid = threadIdx.x, tx = tid & 31, ty = tid >> 5;
    const int w0 = (blockIdx.x & 1) * 32, h0 = (blockIdx.x >> 1) * 8;
    const int d = blockIdx.y % D_, n = blockIdx.y / D_;

    float acc[8];
    #pragma unroll
    for (int c = 0; c < 8; c++) acc[c] = bo[c];

    #pragma unroll 1
    for (int kd = 0; kd < 3; kd++) {
        int zd = d + kd - 1;
        if (zd < 0 || zd >= D_) continue;
        #pragma unroll 1
        for (int cc = 0; cc < 8; cc++) {
            for (int i = tid; i < 8*340; i += 256) {
                int ci = i/340, r = i%340, hy = r/34, wx = r%34;
                int hg = h0-1+hy, wg = w0-1+wx;
                float v = 0.f;
                if (hg >= 0 && hg < H_ && wg >= 0 && wg < W_)
                    v = x[((n*C_ + cc*8+ci)*D_ + zd)*HW_ + hg*W_ + wg];
                xs[ci][hy][wx] = v;
            }
            for (int i = tid; i < 8*9*8; i += 256) {
                int co = i & 7, k = (i >> 3) % 9, ci = i / 72;
                ws[i] = wo[(co*C_ + cc*8+ci)*27 + kd*9 + k];
            }
            __syncthreads();
            #pragma unroll 2
            for (int ci = 0; ci < 8; ci++) {
                float xv[9];
                #pragma unroll
                for (int kh = 0; kh < 3; kh++)
                #pragma unroll
                for (int kw = 0; kw < 3; kw++) xv[kh*3+kw] = xs[ci][ty+kh][tx+kw];
                #pragma unroll
                for (int k = 0; k < 9; k++) {
                    const float4* wp = (const float4*)&ws[(ci*9 + k)*8];
                    #pragma unroll
                    for (int c4 = 0; c4 < 2; c4++) {
                        float4 wv = wp[c4];
                        acc[c4*4+0] += xv[k]*wv.x; acc[c4*4+1] += xv[k]*wv.y;
                        acc[c4*4+2] += xv[k]*wv.z; acc[c4*4+3] += xv[k]*wv.w;
                    }
                }
            }
            __syncthreads();
        }
    }
    int w = w0 + tx, h = h0 + ty;
    if (w < W_) {
        #pragma unroll
        for (int c = 0; c < 8; c++)
            off[((n*G_ + c)*D_ + d)*HW_ + h*W_ + w] = acc[c];
    }
}

// ---------------------------------------------------------------------------
// Deformable conv: t1 = deform_conv(x, off, w1)  + BN1 stats accumulation
// ---------------------------------------------------------------------------
__global__ __launch_bounds__(256) void deform_conv(
    const float* __restrict__ x, const float* __restrict__ off,
    const float* __restrict__ w1)
{
    __shared__ __align__(16) float xs[8][10][34];
    __shared__ __align__(16) float ws[8*9*32];
    __shared__ float offt[8][10][34];
    __shared__ float sstat[64];
    const int tid = threadIdx.x, tx = tid & 31, ty = tid >> 5;
    const int w0 = (blockIdx.x & 1) * 32, h0 = (blockIdx.x >> 1) * 8;
    const int d = blockIdx.y % D_, n = blockIdx.y / D_;
    const int co0 = blockIdx.z * 32;

    for (int i = tid; i < 8*340; i += 256) {
        int g = i/340, r = i%340, hy = r/34, wx = r%34;
        int hg = h0-1+hy, wg = w0-1+wx;
        float v = 0.f;
        if (hg >= 0 && hg < H_ && wg >= 0 && wg < W_)
            v = off[((n*G_ + g)*D_ + d)*HW_ + hg*W_ + wg];
        offt[g][hy][wx] = v;
    }
    if (tid < 64) sstat[tid] = 0.f;

    float acc[32];
    #pragma unroll
    for (int c = 0; c < 32; c++) acc[c] = 0.f;
    __syncthreads();

    #pragma unroll 1
    for (int kd = 0; kd < 3; kd++) {
        #pragma unroll 1
        for (int cc = 0; cc < 8; cc++) {
            for (int i = tid; i < 8*340; i += 256) {
                int ci = i/340, r = i%340, hy = r/34, wx = r%34;
                int hg = h0-1+hy, wg = w0-1+wx;
                float v = 0.f;
                if (hg >= 0 && hg < H_ && wg >= 0 && wg < W_) {
                    int cig = cc*8 + ci;
                    float pos = offt[cig >> 3][hy][wx] + (float)(d + kd - 1);
                    float f0 = floorf(pos);
                    float fr = pos - f0;
                    int i0 = (int)f0;
                    const float* xb = x + ((n*C_ + cig)*D_)*HW_ + hg*W_ + wg;
                    float v0 = (i0   >= 0 && i0   < D_) ? xb[i0*HW_]     : 0.f;
                    float v1 = (i0+1 >= 0 && i0+1 < D_) ? xb[(i0+1)*HW_] : 0.f;
                    v = v0*(1.f-fr) + v1*fr;
                }
                xs[ci][hy][wx] = v;
            }
            for (int i = tid; i < 8*9*32; i += 256) {
                int co = i & 31, k = (i >> 5) % 9, ci = i / 288;
                ws[i] = w1[((co0+co)*C_ + cc*8+ci)*27 + kd*9 + k];
            }
            __syncthreads();
            #pragma unroll 2
            for (int ci = 0; ci < 8; ci++) {
                float xv[9];
                #pragma unroll
                for (int kh = 0; kh < 3; kh++)
                #pragma unroll
                for (int kw = 0; kw < 3; kw++) xv[kh*3+kw] = xs[ci][ty+kh][tx+kw];
                #pragma unroll
                for (int k = 0; k < 9; k++) {
                    const float4* wp = (const float4*)&ws[(ci*9 + k)*32];
                    #pragma unroll
                    for (int c4 = 0; c4 < 8; c4++) {
                        float4 wv = wp[c4];
                        acc[c4*4+0] += xv[k]*wv.x; acc[c4*4+1] += xv[k]*wv.y;
                        acc[c4*4+2] += xv[k]*wv.z; acc[c4*4+3] += xv[k]*wv.w;
                    }
                }
            }
            __syncthreads();
        }
    }
    int w = w0 + tx, h = h0 + ty;
    bool valid = (w < W_);
    float* t1p = g_t1 + ((n*C_ + co0)*D_ + d)*HW_ + h*W_ + w;
    #pragma unroll
    for (int c = 0; c < 32; c++) {
        float v = valid ? acc[c] : 0.f;
        if (valid) t1p[c*DHW_] = v;
        float s = v, q = v*v;
        #pragma unroll
        for (int o = 16; o; o >>= 1) {
            s += __shfl_xor_sync(0xffffffffu, s, o);
            q += __shfl_xor_sync(0xffffffffu, q, o);
        }
        if (tx == 0) { atomicAdd(&sstat[c], s); atomicAdd(&sstat[32+c], q); }
    }
    __syncthreads();
    if (tid < 32) {
        atomicAdd(&g_sum[0][co0+tid], sstat[tid]);
        atomicAdd(&g_sum[1][co0+tid], sstat[32+tid]);
    }
}

// ---------------------------------------------------------------------------
// conv2: t2 = conv3x3x3(relu(bn1(t1)), w2) + b2   + BN2 stats accumulation
// ---------------------------------------------------------------------------
__global__ __launch_bounds__(256) void conv2_k(
    const float* __restrict__ w2, const float* __restrict__ b2)
{
    __shared__ __align__(16) float xs[8][10][34];
    __shared__ __align__(16) float ws[8*9*32];
    __shared__ float sstat[64];
    const int tid = threadIdx.x, tx = tid & 31, ty = tid >> 5;
    const int w0 = (blockIdx.x & 1) * 32, h0 = (blockIdx.x >> 1) * 8;
    const int d = blockIdx.y % D_, n = blockIdx.y / D_;
    const int co0 = blockIdx.z * 32;

    if (tid < 64) sstat[tid] = 0.f;
    float acc[32];
    #pragma unroll
    for (int c = 0; c < 32; c++) acc[c] = b2[co0 + c];
    __syncthreads();

    #pragma unroll 1
    for (int kd = 0; kd < 3; kd++) {
        int zd = d + kd - 1;
        if (zd < 0 || zd >= D_) continue;
        #pragma unroll 1
        for (int cc = 0; cc < 8; cc++) {
            for (int i = tid; i < 8*340; i += 256) {
                int ci = i/340, r = i%340, hy = r/34, wx = r%34;
                int hg = h0-1+hy, wg = w0-1+wx;
                float v = 0.f;
                if (hg >= 0 && hg < H_ && wg >= 0 && wg < W_) {
                    int cig = cc*8 + ci;
                    float t = g_t1[((n*C_ + cig)*D_ + zd)*HW_ + hg*W_ + wg];
                    v = fmaf(g_bn[0][cig], t, g_bn[1][cig]);
                    v = v > 0.f ? v : 0.f;
                }
                xs[ci][hy][wx] = v;
            }
            for (int i = tid; i < 8*9*32; i += 256) {
                int co = i & 31, k = (i >> 5) % 9, ci = i / 288;
                ws[i] = w2[((co0+co)*C_ + cc*8+ci)*27 + kd*9 + k];
            }
            __syncthreads();
            #pragma unroll 2
            for (int ci = 0; ci < 8; ci++) {
                float xv[9];
                #pragma unroll
                for (int kh = 0; kh < 3; kh++)
                #pragma unroll
                for (int kw = 0; kw < 3; kw++) xv[kh*3+kw] = xs[ci][ty+kh][tx+kw];
                #pragma unroll
                for (int k = 0; k < 9; k++) {
                    const float4* wp = (const float4*)&ws[(ci*9 + k)*32];
                    #pragma unroll
                    for (int c4 = 0; c4 < 8; c4++) {
                        float4 wv = wp[c4];
                        acc[c4*4+0] += xv[k]*wv.x; acc[c4*4+1] += xv[k]*wv.y;
                        acc[c4*4+2] += xv[k]*wv.z; acc[c4*4+3] += xv[k]*wv.w;
                    }
                }
            }
            __syncthreads();
        }
    }
    int w = w0 + tx, h = h0 + ty;
    bool valid = (w < W_);
    float* t2p = g_t2 + ((n*C_ + co0)*D_ + d)*HW_ + h*W_ + w;
    #pragma unroll
    for (int c = 0; c < 32; c++) {
        float v = valid ? acc[c] : 0.f;
        if (valid) t2p[c*DHW_] = v;
        float s = v, q = v*v;
        #pragma unroll
        for (int o = 16; o; o >>= 1) {
            s += __shfl_xor_sync(0xffffffffu, s, o);
            q += __shfl_xor_sync(0xffffffffu, q, o);
        }
        if (tx == 0) { atomicAdd(&sstat[c], s); atomicAdd(&sstat[32+c], q); }
    }
    __syncthreads();
    if (tid < 32) {
        atomicAdd(&g_sum[2][co0+tid], sstat[tid]);
        atomicAdd(&g_sum[3][co0+tid], sstat[32+tid]);
    }
}

__global__ void bn_params(const float* __restrict__ gamma,
                          const float* __restrict__ beta, int which)
{
    int c = threadIdx.x;
    if (c < C_) {
        float mean = g_sum[2*which][c] / CNT_;
        float var  = g_sum[2*which+1][c] / CNT_ - mean*mean;
        float r = rsqrtf(var + 1e-5f);
        float sc = gamma[c] * r;
        g_bn[2*which][c]   = sc;
        g_bn[2*which+1][c] = beta[c] - mean*sc;
    }
}

__global__ void final_k(const float* __restrict__ x, float* __restrict__ out)
{
    int idx = blockIdx.x * blockDim.x + threadIdx.x;
    if (idx < XTOT_) {
        int c = (idx / DHW_) % C_;
        float v = fmaf(g_bn[2][c], g_t2[idx], g_bn[3][c]) + x[idx];
        out[idx] = v > 0.f ? v : 0.f;
    }
}

extern "C" void kernel_launch(void* const* d_in, const int* in_sizes, int n_in,
                              void* d_out, int out_size)
{
    const float* x     = (const float*)d_in[0];
    const float* w_off = (const float*)d_in[1];
    const float* b_off = (const float*)d_in[2];
    const float* w1    = (const float*)d_in[3];
    const float* w2    = (const float*)d_in[4];
    const float* b2    = (const float*)d_in[5];
    const float* g1    = (const float*)d_in[6];
    const float* be1   = (const float*)d_in[7];
    const float* g2    = (const float*)d_in[8];
    const float* be2   = (const float*)d_in[9];
    float* out = (float*)d_out;

    // tuple output (out, off): off lives after `out` if the harness packed both
    float* off_ptr;
    if (out_size >= XTOT_ + OFFTOT_) {
        off_ptr = out + XTOT_;
    } else {
        cudaGetSymbolAddress((void**)&off_ptr, g_off);
    }

    zero_stats<<<1, 64>>>();
    offset_conv<<<dim3(14, 128), 256>>>(x, w_off, b_off, off_ptr);
    deform_conv<<<dim3(14, 128, 2), 256>>>(x, off_ptr, w1);
    bn_params<<<1, 64>>>(g1, be1, 0);
    conv2_k<<<dim3(14, 128, 2), 256>>>(w2, b2);
    bn_params<<<1, 64>>>(g2, be2, 1);
    final_k<<<(XTOT_ + 255) / 256, 256>>>(x, out);
}

// round 2
// speedup vs baseline: 1.0463x; 1.0463x over previous
#include <cuda_runtime.h>

#define N_ 8
#define C_ 64
#define D_ 16
#define H_ 56
#define W_ 56
#define G_ 8
#define HW_ (H_*W_)
#define DHW_ (D_*HW_)
#define XTOT_ (N_*C_*DHW_)
#define OFFTOT_ (N_*G_*DHW_)
#define CNT_ ((float)(N_*DHW_))

__device__ float g_t1[XTOT_];
__device__ float g_t2[XTOT_];
__device__ float g_off[OFFTOT_];
__device__ float g_sum[4][C_];
__device__ float g_bn[4][C_];

// ---- packed f32x2 helpers -------------------------------------------------
__device__ __forceinline__ unsigned long long pack2(float x) {
    unsigned long long r;
    asm("mov.b64 %0, {%1, %1};" : "=l"(r) : "f"(x));
    return r;
}
__device__ __forceinline__ unsigned long long pack_pair(float a, float b) {
    unsigned long long r;
    asm("mov.b64 %0, {%1, %2};" : "=l"(r) : "f"(a), "f"(b));
    return r;
}
__device__ __forceinline__ void fma2(unsigned long long& d,
                                     unsigned long long a, unsigned long long b) {
    asm("fma.rn.f32x2 %0, %1, %2, %0;" : "+l"(d) : "l"(a), "l"(b));
}
__device__ __forceinline__ void unpack2(unsigned long long v, float& lo, float& hi) {
    asm("mov.b64 {%0, %1}, %2;" : "=f"(lo), "=f"(hi) : "l"(v));
}

__global__ void zero_stats() {
    int t = threadIdx.x;
    if (t < C_) { g_sum[0][t]=0.f; g_sum[1][t]=0.f; g_sum[2][t]=0.f; g_sum[3][t]=0.f; }
}

// ---------------------------------------------------------------------------
// Offset conv: off = conv3x3x3(x, w_off) + b_off  (8 outputs)
// ---------------------------------------------------------------------------
__global__ __launch_bounds__(256) void offset_conv(
    const float* __restrict__ x, const float* __restrict__ wo,
    const float* __restrict__ bo, float* __restrict__ off)
{
    __shared__ __align__(16) float xs[8][340];
    __shared__ __align__(16) float ws[8*9*8];
    const int tid = threadIdx.x, lane = tid & 31, wid = tid >> 5;
    const int w0 = (blockIdx.x & 1) * 32, h0 = (blockIdx.x >> 1) * 8;
    const int d = blockIdx.y % D_, n = blockIdx.y / D_;

    unsigned long long acc2[4];
    #pragma unroll
    for (int q = 0; q < 4; q++) acc2[q] = pack_pair(bo[2*q], bo[2*q+1]);

    #pragma unroll 1
    for (int kd = 0; kd < 3; kd++) {
        int zd = d + kd - 1;
        if (zd < 0 || zd >= D_) continue;
        #pragma unroll 1
        for (int cc = 0; cc < 8; cc++) {
            __syncthreads();
            const float* xb = x + ((size_t)(n*C_ + cc*8 + wid)*D_ + zd)*HW_;
            for (int r = lane; r < 340; r += 32) {
                int hy = r/34, wx = r%34;
                int hg = h0-1+hy, wg = w0-1+wx;
                float v = 0.f;
                if (hg >= 0 && hg < H_ && wg >= 0 && wg < W_) v = xb[hg*W_ + wg];
                xs[wid][r] = v;
            }
            for (int i = tid; i < 8*9*8; i += 256) {
                int co = i & 7, k = (i >> 3) % 9, ci = i / 72;
                ws[i] = wo[(co*C_ + cc*8+ci)*27 + kd*9 + k];
            }
            __syncthreads();
            #pragma unroll 2
            for (int ci = 0; ci < 8; ci++) {
                float xv[9];
                #pragma unroll
                for (int kh = 0; kh < 3; kh++)
                #pragma unroll
                for (int kw = 0; kw < 3; kw++)
                    xv[kh*3+kw] = xs[ci][(wid+kh)*34 + lane+kw];
                #pragma unroll
                for (int k = 0; k < 9; k++) {
                    unsigned long long xd = pack2(xv[k]);
                    const ulonglong2* wp = (const ulonglong2*)&ws[(ci*9 + k)*8];
                    #pragma unroll
                    for (int q = 0; q < 2; q++) {
                        ulonglong2 wv = wp[q];
                        fma2(acc2[q*2],   xd, wv.x);
                        fma2(acc2[q*2+1], xd, wv.y);
                    }
                }
            }
        }
    }
    int w = w0 + lane, h = h0 + wid;
    if (w < W_) {
        #pragma unroll
        for (int q = 0; q < 4; q++) {
            float lo, hi; unpack2(acc2[q], lo, hi);
            off[((n*G_ + 2*q  )*D_ + d)*HW_ + h*W_ + w] = lo;
            off[((n*G_ + 2*q+1)*D_ + d)*HW_ + h*W_ + w] = hi;
        }
    }
}

// ---------------------------------------------------------------------------
// Deformable conv: t1 = deform_conv(x, off, w1)  + BN1 stats
// ---------------------------------------------------------------------------
__global__ __launch_bounds__(256) void deform_conv(
    const float* __restrict__ x, const float* __restrict__ off,
    const float* __restrict__ w1)
{
    __shared__ __align__(16) float xs[8][340];
    __shared__ __align__(16) float ws[8*9*32];
    __shared__ float offt[8][340];
    __shared__ float sw0[340], sw1[340];
    __shared__ int   so0[340], so1[340];
    __shared__ float sstat[64];
    const int tid = threadIdx.x, lane = tid & 31, wid = tid >> 5;
    const int w0 = (blockIdx.x & 1) * 32, h0 = (blockIdx.x >> 1) * 8;
    const int d = blockIdx.y % D_, n = blockIdx.y / D_;
    const int co0 = blockIdx.z * 32;

    // offset tile: warp wid loads group wid
    {
        const float* ob = off + ((size_t)(n*G_ + wid)*D_ + d)*HW_;
        for (int r = lane; r < 340; r += 32) {
            int hy = r/34, wx = r%34;
            int hg = h0-1+hy, wg = w0-1+wx;
            float v = 0.f;
            if (hg >= 0 && hg < H_ && wg >= 0 && wg < W_) v = ob[hg*W_ + wg];
            offt[wid][r] = v;
        }
    }
    if (tid < 64) sstat[tid] = 0.f;

    unsigned long long acc2[16];
    #pragma unroll
    for (int q = 0; q < 16; q++) acc2[q] = 0ull;
    __syncthreads();

    #pragma unroll 1
    for (int kd = 0; kd < 3; kd++) {
        const float dk = (float)(d + kd - 1);
        #pragma unroll 1
        for (int cc = 0; cc < 8; cc++) {
            // phase 1: interpolation tables (group == cc for this chunk) + weights
            for (int r = tid; r < 340; r += 256) {
                int hy = r/34, wx = r%34;
                int hg = h0-1+hy, wg = w0-1+wx;
                bool sval = (hg >= 0 && hg < H_ && wg >= 0 && wg < W_);
                float pos = offt[cc][r] + dk;
                float f0f = floorf(pos);
                float fr = pos - f0f;
                int i0 = (int)f0f;
                bool m0 = sval && (i0 >= 0) && (i0 < D_);
                bool m1 = sval && (i0+1 >= 0) && (i0+1 < D_);
                int spat = sval ? hg*W_ + wg : 0;
                so0[r] = (m0 ? i0     : 0)*HW_ + spat;
                so1[r] = (m1 ? (i0+1) : 0)*HW_ + spat;
                sw0[r] = m0 ? (1.f - fr) : 0.f;
                sw1[r] = m1 ? fr : 0.f;
            }
            for (int i = tid; i < 8*9*32; i += 256) {
                int co = i & 31, k = (i >> 5) % 9, ci = i / 288;
                ws[i] = w1[((size_t)(co0+co)*C_ + cc*8+ci)*27 + kd*9 + k];
            }
            __syncthreads();
            // phase 2: gather x tile (warp-per-ci, cheap 2xLDG + lerp)
            {
                const float* xb = x + (size_t)(n*C_ + cc*8 + wid)*DHW_;
                for (int r = lane; r < 340; r += 32)
                    xs[wid][r] = xb[so0[r]]*sw0[r] + xb[so1[r]]*sw1[r];
            }
            __syncthreads();
            // phase 3: compute
            #pragma unroll 2
            for (int ci = 0; ci < 8; ci++) {
                float xv[9];
                #pragma unroll
                for (int kh = 0; kh < 3; kh++)
                #pragma unroll
                for (int kw = 0; kw < 3; kw++)
                    xv[kh*3+kw] = xs[ci][(wid+kh)*34 + lane+kw];
                #pragma unroll
                for (int k = 0; k < 9; k++) {
                    unsigned long long xd = pack2(xv[k]);
                    const ulonglong2* wp = (const ulonglong2*)&ws[(ci*9 + k)*32];
                    #pragma unroll
                    for (int q = 0; q < 8; q++) {
                        ulonglong2 wv = wp[q];
                        fma2(acc2[q*2],   xd, wv.x);
                        fma2(acc2[q*2+1], xd, wv.y);
                    }
                }
            }
            __syncthreads();
        }
    }
    int w = w0 + lane, h = h0 + wid;
    bool valid = (w < W_);
    float* t1p = g_t1 + ((size_t)(n*C_ + co0)*D_ + d)*HW_ + h*W_ + w;
    #pragma unroll
    for (int q = 0; q < 16; q++) {
        float v[2]; unpack2(acc2[q], v[0], v[1]);
        #pragma unroll
        for (int u = 0; u < 2; u++) {
            int c = 2*q + u;
            float vv = valid ? v[u] : 0.f;
            if (valid) t1p[c*DHW_] = vv;
            float s = vv, sq = vv*vv;
            #pragma unroll
            for (int o = 16; o; o >>= 1) {
                s  += __shfl_xor_sync(0xffffffffu, s,  o);
                sq += __shfl_xor_sync(0xffffffffu, sq, o);
            }
            if (lane == 0) { atomicAdd(&sstat[c], s); atomicAdd(&sstat[32+c], sq); }
        }
    }
    __syncthreads();
    if (tid < 32) {
        atomicAdd(&g_sum[0][co0+tid], sstat[tid]);
        atomicAdd(&g_sum[1][co0+tid], sstat[32+tid]);
    }
}

// ---------------------------------------------------------------------------
// conv2: t2 = conv3x3x3(relu(bn1(t1)), w2) + b2  + BN2 stats
// ---------------------------------------------------------------------------
__global__ __launch_bounds__(256) void conv2_k(
    const float* __restrict__ w2, const float* __restrict__ b2)
{
    __shared__ __align__(16) float xs[8][340];
    __shared__ __align__(16) float ws[8*9*32];
    __shared__ float sstat[64];
    const int tid = threadIdx.x, lane = tid & 31, wid = tid >> 5;
    const int w0 = (blockIdx.x & 1) * 32, h0 = (blockIdx.x >> 1) * 8;
    const int d = blockIdx.y % D_, n = blockIdx.y / D_;
    const int co0 = blockIdx.z * 32;

    if (tid < 64) sstat[tid] = 0.f;
    unsigned long long acc2[16];
    #pragma unroll
    for (int q = 0; q < 16; q++) acc2[q] = pack_pair(b2[co0+2*q], b2[co0+2*q+1]);
    __syncthreads();

    #pragma unroll 1
    for (int kd = 0; kd < 3; kd++) {
        int zd = d + kd - 1;
        if (zd < 0 || zd >= D_) continue;
        #pragma unroll 1
        for (int cc = 0; cc < 8; cc++) {
            __syncthreads();
            {
                int cig = cc*8 + wid;
                const float* tb = g_t1 + ((size_t)(n*C_ + cig)*D_ + zd)*HW_;
                float sc = g_bn[0][cig], sh = g_bn[1][cig];
                for (int r = lane; r < 340; r += 32) {
                    int hy = r/34, wx = r%34;
                    int hg = h0-1+hy, wg = w0-1+wx;
                    float v = 0.f;
                    if (hg >= 0 && hg < H_ && wg >= 0 && wg < W_) {
                        v = fmaf(sc, tb[hg*W_ + wg], sh);
                        v = v > 0.f ? v : 0.f;
                    }
                    xs[wid][r] = v;
                }
            }
            for (int i = tid; i < 8*9*32; i += 256) {
                int co = i & 31, k = (i >> 5) % 9, ci = i / 288;
                ws[i] = w2[((size_t)(co0+co)*C_ + cc*8+ci)*27 + kd*9 + k];
            }
            __syncthreads();
            #pragma unroll 2
            for (int ci = 0; ci < 8; ci++) {
                float xv[9];
                #pragma unroll
                for (int kh = 0; kh < 3; kh++)
                #pragma unroll
                for (int kw = 0; kw < 3; kw++)
                    xv[kh*3+kw] = xs[ci][(wid+kh)*34 + lane+kw];
                #pragma unroll
                for (int k = 0; k < 9; k++) {
                    unsigned long long xd = pack2(xv[k]);
                    const ulonglong2* wp = (const ulonglong2*)&ws[(ci*9 + k)*32];
                    #pragma unroll
                    for (int q = 0; q < 8; q++) {
                        ulonglong2 wv = wp[q];
                        fma2(acc2[q*2],   xd, wv.x);
                        fma2(acc2[q*2+1], xd, wv.y);
                    }
                }
            }
        }
    }
    int w = w0 + lane, h = h0 + wid;
    bool valid = (w < W_);
    float* t2p = g_t2 + ((size_t)(n*C_ + co0)*D_ + d)*HW_ + h*W_ + w;
    #pragma unroll
    for (int q = 0; q < 16; q++) {
        float v[2]; unpack2(acc2[q], v[0], v[1]);
        #pragma unroll
        for (int u = 0; u < 2; u++) {
            int c = 2*q + u;
            float vv = valid ? v[u] : 0.f;
            if (valid) t2p[c*DHW_] = vv;
            float s = vv, sq = vv*vv;
            #pragma unroll
            for (int o = 16; o; o >>= 1) {
                s  += __shfl_xor_sync(0xffffffffu, s,  o);
                sq += __shfl_xor_sync(0xffffffffu, sq, o);
            }
            if (lane == 0) { atomicAdd(&sstat[c], s); atomicAdd(&sstat[32+c], sq); }
        }
    }
    __syncthreads();
    if (tid < 32) {
        atomicAdd(&g_sum[2][co0+tid], sstat[tid]);
        atomicAdd(&g_sum[3][co0+tid], sstat[32+tid]);
    }
}

__global__ void bn_params(const float* __restrict__ gamma,
                          const float* __restrict__ beta, int which)
{
    int c = threadIdx.x;
    if (c < C_) {
        float mean = g_sum[2*which][c] / CNT_;
        float var  = g_sum[2*which+1][c] / CNT_ - mean*mean;
        float r = rsqrtf(var + 1e-5f);
        float sc = gamma[c] * r;
        g_bn[2*which][c]   = sc;
        g_bn[2*which+1][c] = beta[c] - mean*sc;
    }
}

__global__ void final_k(const float* __restrict__ x, float* __restrict__ out)
{
    int i4 = blockIdx.x * blockDim.x + threadIdx.x;
    if (i4 < XTOT_/4) {
        int c = (i4 / (DHW_/4)) % C_;
        float sc = g_bn[2][c], sh = g_bn[3][c];
        float4 t = ((const float4*)g_t2)[i4];
        float4 xv = ((const float4*)x)[i4];
        float4 o;
        o.x = fmaf(sc, t.x, sh) + xv.x; o.x = o.x > 0.f ? o.x : 0.f;
        o.y = fmaf(sc, t.y, sh) + xv.y; o.y = o.y > 0.f ? o.y : 0.f;
        o.z = fmaf(sc, t.z, sh) + xv.z; o.z = o.z > 0.f ? o.z : 0.f;
        o.w = fmaf(sc, t.w, sh) + xv.w; o.w = o.w > 0.f ? o.w : 0.f;
        ((float4*)out)[i4] = o;
    }
}

extern "C" void kernel_launch(void* const* d_in, const int* in_sizes, int n_in,
                              void* d_out, int out_size)
{
    const float* x     = (const float*)d_in[0];
    const float* w_off = (const float*)d_in[1];
    const float* b_off = (const float*)d_in[2];
    const float* w1    = (const float*)d_in[3];
    const float* w2    = (const float*)d_in[4];
    const float* b2    = (const float*)d_in[5];
    const float* g1    = (const float*)d_in[6];
    const float* be1   = (const float*)d_in[7];
    const float* g2    = (const float*)d_in[8];
    const float* be2   = (const float*)d_in[9];
    float* out = (float*)d_out;

    float* off_ptr;
    if (out_size >= XTOT_ + OFFTOT_) {
        off_ptr = out + XTOT_;
    } else {
        cudaGetSymbolAddress((void**)&off_ptr, g_off);
    }

    zero_stats<<<1, 64>>>();
    offset_conv<<<dim3(14, 128), 256>>>(x, w_off, b_off, off_ptr);
    deform_conv<<<dim3(14, 128, 2), 256>>>(x, off_ptr, w1);
    bn_params<<<1, 64>>>(g1, be1, 0);
    conv2_k<<<dim3(14, 128, 2), 256>>>(w2, b2);
    bn_params<<<1, 64>>>(g2, be2, 1);
    final_k<<<(XTOT_/4 + 255) / 256, 256>>>(x, out);
}

// round 3
// speedup vs baseline: 1.0473x; 1.0009x over previous
#include <cuda_runtime.h>

#define N_ 8
#define C_ 64
#define D_ 16
#define H_ 56
#define W_ 56
#define G_ 8
#define HW_ (H_*W_)
#define DHW_ (D_*HW_)
#define XTOT_ (N_*C_*DHW_)
#define OFFTOT_ (N_*G_*DHW_)
#define CNT_ ((float)(N_*DHW_))

__device__ float g_t1[XTOT_];
__device__ float g_t2[XTOT_];
__device__ float g_off[OFFTOT_];
__device__ float g_sum[4][C_];
__device__ float g_bn[4][C_];

// ---- packed f32x2 helpers -------------------------------------------------
__device__ __forceinline__ unsigned long long pack2(float x) {
    unsigned long long r;
    asm("mov.b64 %0, {%1, %1};" : "=l"(r) : "f"(x));
    return r;
}
__device__ __forceinline__ unsigned long long pack_pair(float a, float b) {
    unsigned long long r;
    asm("mov.b64 %0, {%1, %2};" : "=l"(r) : "f"(a), "f"(b));
    return r;
}
__device__ __forceinline__ void fma2(unsigned long long& d,
                                     unsigned long long a, unsigned long long b) {
    asm("fma.rn.f32x2 %0, %1, %2, %0;" : "+l"(d) : "l"(a), "l"(b));
}
__device__ __forceinline__ void unpack2(unsigned long long v, float& lo, float& hi) {
    asm("mov.b64 {%0, %1}, %2;" : "=f"(lo), "=f"(hi) : "l"(v));
}

__global__ void zero_stats() {
    int t = threadIdx.x;
    if (t < C_) { g_sum[0][t]=0.f; g_sum[1][t]=0.f; g_sum[2][t]=0.f; g_sum[3][t]=0.f; }
}

// ---------------------------------------------------------------------------
// Offset conv: off = conv3x3x3(x, w_off) + b_off  (8 outputs)
// ---------------------------------------------------------------------------
__global__ __launch_bounds__(256) void offset_conv(
    const float* __restrict__ x, const float* __restrict__ wo,
    const float* __restrict__ bo, float* __restrict__ off)
{
    __shared__ __align__(16) float xs[8][340];
    __shared__ __align__(16) float ws[8*9*8];
    const int tid = threadIdx.x, lane = tid & 31, wid = tid >> 5;
    const int w0 = (blockIdx.x & 1) * 32, h0 = (blockIdx.x >> 1) * 8;
    const int d = blockIdx.y % D_, n = blockIdx.y / D_;

    unsigned long long acc2[4];
    #pragma unroll
    for (int q = 0; q < 4; q++) acc2[q] = pack_pair(bo[2*q], bo[2*q+1]);

    #pragma unroll 1
    for (int kd = 0; kd < 3; kd++) {
        int zd = d + kd - 1;
        if (zd < 0 || zd >= D_) continue;
        #pragma unroll 1
        for (int cc = 0; cc < 8; cc++) {
            __syncthreads();
            const float* xb = x + ((size_t)(n*C_ + cc*8 + wid)*D_ + zd)*HW_;
            for (int r = lane; r < 340; r += 32) {
                int hy = r/34, wx = r%34;
                int hg = h0-1+hy, wg = w0-1+wx;
                float v = 0.f;
                if (hg >= 0 && hg < H_ && wg >= 0 && wg < W_) v = xb[hg*W_ + wg];
                xs[wid][r] = v;
            }
            for (int i = tid; i < 8*9*8; i += 256) {
                int co = i & 7, k = (i >> 3) % 9, ci = i / 72;
                ws[i] = wo[(co*C_ + cc*8+ci)*27 + kd*9 + k];
            }
            __syncthreads();
            #pragma unroll 2
            for (int ci = 0; ci < 8; ci++) {
                float xv[9];
                #pragma unroll
                for (int kh = 0; kh < 3; kh++)
                #pragma unroll
                for (int kw = 0; kw < 3; kw++)
                    xv[kh*3+kw] = xs[ci][(wid+kh)*34 + lane+kw];
                #pragma unroll
                for (int k = 0; k < 9; k++) {
                    unsigned long long xd = pack2(xv[k]);
                    const ulonglong2* wp = (const ulonglong2*)&ws[(ci*9 + k)*8];
                    #pragma unroll
                    for (int q = 0; q < 2; q++) {
                        ulonglong2 wv = wp[q];
                        fma2(acc2[q*2],   xd, wv.x);
                        fma2(acc2[q*2+1], xd, wv.y);
                    }
                }
            }
        }
    }
    int w = w0 + lane, h = h0 + wid;
    if (w < W_) {
        #pragma unroll
        for (int q = 0; q < 4; q++) {
            float lo, hi; unpack2(acc2[q], lo, hi);
            off[((n*G_ + 2*q  )*D_ + d)*HW_ + h*W_ + w] = lo;
            off[((n*G_ + 2*q+1)*D_ + d)*HW_ + h*W_ + w] = hi;
        }
    }
}

// ---------------------------------------------------------------------------
// Deformable conv: t1 = deform_conv(x, off, w1)  + BN1 stats
// ---------------------------------------------------------------------------
__global__ __launch_bounds__(256) void deform_conv(
    const float* __restrict__ x, const float* __restrict__ off,
    const float* __restrict__ w1)
{
    __shared__ __align__(16) float xs[8][340];
    __shared__ __align__(16) float ws[8*9*32];
    __shared__ float offt[8][340];
    __shared__ float sw0[340], sw1[340];
    __shared__ int   so0[340], so1[340];
    __shared__ float sstat[64];
    const int tid = threadIdx.x, lane = tid & 31, wid = tid >> 5;
    const int w0 = (blockIdx.x & 1) * 32, h0 = (blockIdx.x >> 1) * 8;
    const int d = blockIdx.y % D_, n = blockIdx.y / D_;
    const int co0 = blockIdx.z * 32;

    // offset tile: warp wid loads group wid
    {
        const float* ob = off + ((size_t)(n*G_ + wid)*D_ + d)*HW_;
        for (int r = lane; r < 340; r += 32) {
            int hy = r/34, wx = r%34;
            int hg = h0-1+hy, wg = w0-1+wx;
            float v = 0.f;
            if (hg >= 0 && hg < H_ && wg >= 0 && wg < W_) v = ob[hg*W_ + wg];
            offt[wid][r] = v;
        }
    }
    if (tid < 64) sstat[tid] = 0.f;

    unsigned long long acc2[16];
    #pragma unroll
    for (int q = 0; q < 16; q++) acc2[q] = 0ull;
    __syncthreads();

    #pragma unroll 1
    for (int kd = 0; kd < 3; kd++) {
        const float dk = (float)(d + kd - 1);
        #pragma unroll 1
        for (int cc = 0; cc < 8; cc++) {
            // phase 1: interpolation tables (group == cc for this chunk) + weights
            for (int r = tid; r < 340; r += 256) {
                int hy = r/34, wx = r%34;
                int hg = h0-1+hy, wg = w0-1+wx;
                bool sval = (hg >= 0 && hg < H_ && wg >= 0 && wg < W_);
                float pos = offt[cc][r] + dk;
                float f0f = floorf(pos);
                float fr = pos - f0f;
                int i0 = (int)f0f;
                bool m0 = sval && (i0 >= 0) && (i0 < D_);
                bool m1 = sval && (i0+1 >= 0) && (i0+1 < D_);
                int spat = sval ? hg*W_ + wg : 0;
                so0[r] = (m0 ? i0     : 0)*HW_ + spat;
                so1[r] = (m1 ? (i0+1) : 0)*HW_ + spat;
                sw0[r] = m0 ? (1.f - fr) : 0.f;
                sw1[r] = m1 ? fr : 0.f;
            }
            for (int i = tid; i < 8*9*32; i += 256) {
                int co = i & 31, k = (i >> 5) % 9, ci = i / 288;
                ws[i] = w1[((size_t)(co0+co)*C_ + cc*8+ci)*27 + kd*9 + k];
            }
            __syncthreads();
            // phase 2: gather x tile (warp-per-ci, cheap 2xLDG + lerp)
            {
                const float* xb = x + (size_t)(n*C_ + cc*8 + wid)*DHW_;
                for (int r = lane; r < 340; r += 32)
                    xs[wid][r] = xb[so0[r]]*sw0[r] + xb[so1[r]]*sw1[r];
            }
            __syncthreads();
            // phase 3: compute
            #pragma unroll 2
            for (int ci = 0; ci < 8; ci++) {
                float xv[9];
                #pragma unroll
                for (int kh = 0; kh < 3; kh++)
                #pragma unroll
                for (int kw = 0; kw < 3; kw++)
                    xv[kh*3+kw] = xs[ci][(wid+kh)*34 + lane+kw];
                #pragma unroll
                for (int k = 0; k < 9; k++) {
                    unsigned long long xd = pack2(xv[k]);
                    const ulonglong2* wp = (const ulonglong2*)&ws[(ci*9 + k)*32];
                    #pragma unroll
                    for (int q = 0; q < 8; q++) {
                        ulonglong2 wv = wp[q];
                        fma2(acc2[q*2],   xd, wv.x);
                        fma2(acc2[q*2+1], xd, wv.y);
                    }
                }
            }
            __syncthreads();
        }
    }
    int w = w0 + lane, h = h0 + wid;
    bool valid = (w < W_);
    float* t1p = g_t1 + ((size_t)(n*C_ + co0)*D_ + d)*HW_ + h*W_ + w;
    #pragma unroll
    for (int q = 0; q < 16; q++) {
        float v[2]; unpack2(acc2[q], v[0], v[1]);
        #pragma unroll
        for (int u = 0; u < 2; u++) {
            int c = 2*q + u;
            float vv = valid ? v[u] : 0.f;
            if (valid) t1p[c*DHW_] = vv;
            float s = vv, sq = vv*vv;
            #pragma unroll
            for (int o = 16; o; o >>= 1) {
                s  += __shfl_xor_sync(0xffffffffu, s,  o);
                sq += __shfl_xor_sync(0xffffffffu, sq, o);
            }
            if (lane == 0) { atomicAdd(&sstat[c], s); atomicAdd(&sstat[32+c], sq); }
        }
    }
    __syncthreads();
    if (tid < 32) {
        atomicAdd(&g_sum[0][co0+tid], sstat[tid]);
        atomicAdd(&g_sum[1][co0+tid], sstat[32+tid]);
    }
}

// ---------------------------------------------------------------------------
// conv2: t2 = conv3x3x3(relu(bn1(t1)), w2) + b2  + BN2 stats
// ---------------------------------------------------------------------------
__global__ __launch_bounds__(256) void conv2_k(
    const float* __restrict__ w2, const float* __restrict__ b2)
{
    __shared__ __align__(16) float xs[8][340];
    __shared__ __align__(16) float ws[8*9*32];
    __shared__ float sstat[64];
    const int tid = threadIdx.x, lane = tid & 31, wid = tid >> 5;
    const int w0 = (blockIdx.x & 1) * 32, h0 = (blockIdx.x >> 1) * 8;
    const int d = blockIdx.y % D_, n = blockIdx.y / D_;
    const int co0 = blockIdx.z * 32;

    if (tid < 64) sstat[tid] = 0.f;
    unsigned long long acc2[16];
    #pragma unroll
    for (int q = 0; q < 16; q++) acc2[q] = pack_pair(b2[co0+2*q], b2[co0+2*q+1]);
    __syncthreads();

    #pragma unroll 1
    for (int kd = 0; kd < 3; kd++) {
        int zd = d + kd - 1;
        if (zd < 0 || zd >= D_) continue;
        #pragma unroll 1
        for (int cc = 0; cc < 8; cc++) {
            __syncthreads();
            {
                int cig = cc*8 + wid;
                const float* tb = g_t1 + ((size_t)(n*C_ + cig)*D_ + zd)*HW_;
                float sc = g_bn[0][cig], sh = g_bn[1][cig];
                for (int r = lane; r < 340; r += 32) {
                    int hy = r/34, wx = r%34;
                    int hg = h0-1+hy, wg = w0-1+wx;
                    float v = 0.f;
                    if (hg >= 0 && hg < H_ && wg >= 0 && wg < W_) {
                        v = fmaf(sc, tb[hg*W_ + wg], sh);
                        v = v > 0.f ? v : 0.f;
                    }
                    xs[wid][r] = v;
                }
            }
            for (int i = tid; i < 8*9*32; i += 256) {
                int co = i & 31, k = (i >> 5) % 9, ci = i / 288;
                ws[i] = w2[((size_t)(co0+co)*C_ + cc*8+ci)*27 + kd*9 + k];
            }
            __syncthreads();
            #pragma unroll 2
            for (int ci = 0; ci < 8; ci++) {
                float xv[9];
                #pragma unroll
                for (int kh = 0; kh < 3; kh++)
                #pragma unroll
                for (int kw = 0; kw < 3; kw++)
                    xv[kh*3+kw] = xs[ci][(wid+kh)*34 + lane+kw];
                #pragma unroll
                for (int k = 0; k < 9; k++) {
                    unsigned long long xd = pack2(xv[k]);
                    const ulonglong2* wp = (const ulonglong2*)&ws[(ci*9 + k)*32];
                    #pragma unroll
                    for (int q = 0; q < 8; q++) {
                        ulonglong2 wv = wp[q];
                        fma2(acc2[q*2],   xd, wv.x);
                        fma2(acc2[q*2+1], xd, wv.y);
                    }
                }
            }
        }
    }
    int w = w0 + lane, h = h0 + wid;
    bool valid = (w < W_);
    float* t2p = g_t2 + ((size_t)(n*C_ + co0)*D_ + d)*HW_ + h*W_ + w;
    #pragma unroll
    for (int q = 0; q < 16; q++) {
        float v[2]; unpack2(acc2[q], v[0], v[1]);
        #pragma unroll
        for (int u = 0; u < 2; u++) {
            int c = 2*q + u;
            float vv = valid ? v[u] : 0.f;
            if (valid) t2p[c*DHW_] = vv;
            float s = vv, sq = vv*vv;
            #pragma unroll
            for (int o = 16; o; o >>= 1) {
                s  += __shfl_xor_sync(0xffffffffu, s,  o);
                sq += __shfl_xor_sync(0xffffffffu, sq, o);
            }
            if (lane == 0) { atomicAdd(&sstat[c], s); atomicAdd(&sstat[32+c], sq); }
        }
    }
    __syncthreads();
    if (tid < 32) {
        atomicAdd(&g_sum[2][co0+tid], sstat[tid]);
        atomicAdd(&g_sum[3][co0+tid], sstat[32+tid]);
    }
}

__global__ void bn_params(const float* __restrict__ gamma,
                          const float* __restrict__ beta, int which)
{
    int c = threadIdx.x;
    if (c < C_) {
        float mean = g_sum[2*which][c] / CNT_;
        float var  = g_sum[2*which+1][c] / CNT_ - mean*mean;
        float r = rsqrtf(var + 1e-5f);
        float sc = gamma[c] * r;
        g_bn[2*which][c]   = sc;
        g_bn[2*which+1][c] = beta[c] - mean*sc;
    }
}

__global__ void final_k(const float* __restrict__ x, float* __restrict__ out)
{
    int i4 = blockIdx.x * blockDim.x + threadIdx.x;
    if (i4 < XTOT_/4) {
        int c = (i4 / (DHW_/4)) % C_;
        float sc = g_bn[2][c], sh = g_bn[3][c];
        float4 t = ((const float4*)g_t2)[i4];
        float4 xv = ((const float4*)x)[i4];
        float4 o;
        o.x = fmaf(sc, t.x, sh) + xv.x; o.x = o.x > 0.f ? o.x : 0.f;
        o.y = fmaf(sc, t.y, sh) + xv.y; o.y = o.y > 0.f ? o.y : 0.f;
        o.z = fmaf(sc, t.z, sh) + xv.z; o.z = o.z > 0.f ? o.z : 0.f;
        o.w = fmaf(sc, t.w, sh) + xv.w; o.w = o.w > 0.f ? o.w : 0.f;
        ((float4*)out)[i4] = o;
    }
}

extern "C" void kernel_launch(void* const* d_in, const int* in_sizes, int n_in,
                              void* d_out, int out_size)
{
    const float* x     = (const float*)d_in[0];
    const float* w_off = (const float*)d_in[1];
    const float* b_off = (const float*)d_in[2];
    const float* w1    = (const float*)d_in[3];
    const float* w2    = (const float*)d_in[4];
    const float* b2    = (const float*)d_in[5];
    const float* g1    = (const float*)d_in[6];
    const float* be1   = (const float*)d_in[7];
    const float* g2    = (const float*)d_in[8];
    const float* be2   = (const float*)d_in[9];
    float* out = (float*)d_out;

    float* off_ptr;
    if (out_size >= XTOT_ + OFFTOT_) {
        off_ptr = out + XTOT_;
    } else {
        cudaGetSymbolAddress((void**)&off_ptr, g_off);
    }

    zero_stats<<<1, 64>>>();
    offset_conv<<<dim3(14, 128), 256>>>(x, w_off, b_off, off_ptr);
    deform_conv<<<dim3(14, 128, 2), 256>>>(x, off_ptr, w1);
    bn_params<<<1, 64>>>(g1, be1, 0);
    conv2_k<<<dim3(14, 128, 2), 256>>>(w2, b2);
    bn_params<<<1, 64>>>(g2, be2, 1);
    final_k<<<(XTOT_/4 + 255) / 256, 256>>>(x, out);
}

// round 4
// speedup vs baseline: 1.5670x; 1.4962x over previous
#include <cuda_runtime.h>
#include <cuda_bf16.h>
#include <cstdint>

#define N_ 8
#define C_ 64
#define D_ 16
#define H_ 56
#define W_ 56
#define G_ 8
#define HW_ (H_*W_)
#define DHW_ (D_*HW_)
#define XTOT_ (N_*C_*DHW_)
#define OFFTOT_ (N_*G_*DHW_)
#define CNT_ ((float)(N_*DHW_))

__device__ float g_t1[XTOT_];
__device__ float g_t2[XTOT_];
__device__ float g_off[OFFTOT_];
__device__ float g_sum[4][C_];
__device__ float g_bn[4][C_];
__device__ __nv_bfloat16 g_uhi[XTOT_];   // NDHWC: ((n*D+d)*H+h)*W+w)*64 + c
__device__ __nv_bfloat16 g_ulo[XTOT_];
__device__ uint32_t g_wb[27*4096];       // per-tap pre-swizzled B fragments

// ---- helpers --------------------------------------------------------------
__device__ __forceinline__ unsigned long long pack2(float x) {
    unsigned long long r;
    asm("mov.b64 %0, {%1, %1};" : "=l"(r) : "f"(x));
    return r;
}
__device__ __forceinline__ unsigned long long pack_pair(float a, float b) {
    unsigned long long r;
    asm("mov.b64 %0, {%1, %2};" : "=l"(r) : "f"(a), "f"(b));
    return r;
}
__device__ __forceinline__ void fma2(unsigned long long& d,
                                     unsigned long long a, unsigned long long b) {
    asm("fma.rn.f32x2 %0, %1, %2, %0;" : "+l"(d) : "l"(a), "l"(b));
}
__device__ __forceinline__ void unpack2(unsigned long long v, float& lo, float& hi) {
    asm("mov.b64 {%0, %1}, %2;" : "=f"(lo), "=f"(hi) : "l"(v));
}
__device__ __forceinline__ uint32_t smem_u32(const void* p) {
    uint32_t a;
    asm("{ .reg .u64 t; cvta.to.shared.u64 t, %1; cvt.u32.u64 %0, t; }" : "=r"(a) : "l"(p));
    return a;
}
__device__ __forceinline__ void cp16(uint32_t dst, const void* src) {
    asm volatile("cp.async.cg.shared.global [%0], [%1], 16;" :: "r"(dst), "l"(src) : "memory");
}
__device__ __forceinline__ void cp16z(uint32_t dst, const void* src, int sz) {
    asm volatile("cp.async.cg.shared.global [%0], [%1], 16, %2;" :: "r"(dst), "l"(src), "r"(sz) : "memory");
}
__device__ __forceinline__ void cp_commit() {
    asm volatile("cp.async.commit_group;" ::: "memory");
}
__device__ __forceinline__ void cp_wait0() {
    asm volatile("cp.async.wait_group 0;" ::: "memory");
}
__device__ __forceinline__ void cp_wait1() {
    asm volatile("cp.async.wait_group 1;" ::: "memory");
}
__device__ __forceinline__ void ldsm4(uint32_t* r, uint32_t addr) {
    asm volatile("ldmatrix.sync.aligned.m8n8.x4.shared.b16 {%0,%1,%2,%3}, [%4];"
                 : "=r"(r[0]), "=r"(r[1]), "=r"(r[2]), "=r"(r[3]) : "r"(addr));
}
__device__ __forceinline__ void mma_bf16(float* d, const uint32_t* a, uint32_t b0, uint32_t b1) {
    asm volatile("mma.sync.aligned.m16n8k16.row.col.f32.bf16.bf16.f32 "
                 "{%0,%1,%2,%3}, {%4,%5,%6,%7}, {%8,%9}, {%0,%1,%2,%3};"
                 : "+f"(d[0]), "+f"(d[1]), "+f"(d[2]), "+f"(d[3])
                 : "r"(a[0]), "r"(a[1]), "r"(a[2]), "r"(a[3]), "r"(b0), "r"(b1));
}
__device__ __forceinline__ uint32_t pack_bf(__nv_bfloat16 a, __nv_bfloat16 b) {
    return (uint32_t)__bfloat16_as_ushort(a) | ((uint32_t)__bfloat16_as_ushort(b) << 16);
}

// ---------------------------------------------------------------------------
// wprep: w2 -> per-lane B-fragment order  +  zero stats
// g_wb[tap][plane(2)][s(4)][nb(8)][lane(32)][2]  (u32 each = 2 bf16, low=even k)
// ---------------------------------------------------------------------------
__global__ void wprep(const float* __restrict__ w2) {
    if (blockIdx.x == 0 && threadIdx.x < C_) {
        g_sum[0][threadIdx.x]=0.f; g_sum[1][threadIdx.x]=0.f;
        g_sum[2][threadIdx.x]=0.f; g_sum[3][threadIdx.x]=0.f;
    }
    int t = blockIdx.x * 256 + threadIdx.x;
    if (t >= 27*4*8*32) return;
    int l = t & 31, nb = (t >> 5) & 7, s = (t >> 8) & 3, tap = t >> 10;
    int g = l >> 2, tg = l & 3;
    int co = nb*8 + g;
    int k0 = s*16 + 2*tg;
    float w00 = w2[(co*64 + k0    )*27 + tap];
    float w01 = w2[(co*64 + k0 + 1)*27 + tap];
    float w10 = w2[(co*64 + k0 + 8)*27 + tap];
    float w11 = w2[(co*64 + k0 + 9)*27 + tap];
    __nv_bfloat16 h00=__float2bfloat16(w00), h01=__float2bfloat16(w01);
    __nv_bfloat16 h10=__float2bfloat16(w10), h11=__float2bfloat16(w11);
    __nv_bfloat16 l00=__float2bfloat16(w00-__bfloat162float(h00));
    __nv_bfloat16 l01=__float2bfloat16(w01-__bfloat162float(h01));
    __nv_bfloat16 l10=__float2bfloat16(w10-__bfloat162float(h10));
    __nv_bfloat16 l11=__float2bfloat16(w11-__bfloat162float(h11));
    uint32_t base = tap*4096 + (s*8 + nb)*64 + l*2;
    g_wb[base + 0]        = pack_bf(h00, h01);
    g_wb[base + 1]        = pack_bf(h10, h11);
    g_wb[base + 2048 + 0] = pack_bf(l00, l01);
    g_wb[base + 2048 + 1] = pack_bf(l10, l11);
}

// ---------------------------------------------------------------------------
// Offset conv (unchanged from R2)
// ---------------------------------------------------------------------------
__global__ __launch_bounds__(256) void offset_conv(
    const float* __restrict__ x, const float* __restrict__ wo,
    const float* __restrict__ bo, float* __restrict__ off)
{
    __shared__ __align__(16) float xs[8][340];
    __shared__ __align__(16) float ws[8*9*8];
    const int tid = threadIdx.x, lane = tid & 31, wid = tid >> 5;
    const int w0 = (blockIdx.x & 1) * 32, h0 = (blockIdx.x >> 1) * 8;
    const int d = blockIdx.y % D_, n = blockIdx.y / D_;

    unsigned long long acc2[4];
    #pragma unroll
    for (int q = 0; q < 4; q++) acc2[q] = pack_pair(bo[2*q], bo[2*q+1]);

    #pragma unroll 1
    for (int kd = 0; kd < 3; kd++) {
        int zd = d + kd - 1;
        if (zd < 0 || zd >= D_) continue;
        #pragma unroll 1
        for (int cc = 0; cc < 8; cc++) {
            __syncthreads();
            const float* xb = x + ((size_t)(n*C_ + cc*8 + wid)*D_ + zd)*HW_;
            for (int r = lane; r < 340; r += 32) {
                int hy = r/34, wx = r%34;
                int hg = h0-1+hy, wg = w0-1+wx;
                float v = 0.f;
                if (hg >= 0 && hg < H_ && wg >= 0 && wg < W_) v = xb[hg*W_ + wg];
                xs[wid][r] = v;
            }
            for (int i = tid; i < 8*9*8; i += 256) {
                int co = i & 7, k = (i >> 3) % 9, ci = i / 72;
                ws[i] = wo[(co*C_ + cc*8+ci)*27 + kd*9 + k];
            }
            __syncthreads();
            #pragma unroll 2
            for (int ci = 0; ci < 8; ci++) {
                float xv[9];
                #pragma unroll
                for (int kh = 0; kh < 3; kh++)
                #pragma unroll
                for (int kw = 0; kw < 3; kw++)
                    xv[kh*3+kw] = xs[ci][(wid+kh)*34 + lane+kw];
                #pragma unroll
                for (int k = 0; k < 9; k++) {
                    unsigned long long xd = pack2(xv[k]);
                    const ulonglong2* wp = (const ulonglong2*)&ws[(ci*9 + k)*8];
                    #pragma unroll
                    for (int q = 0; q < 2; q++) {
                        ulonglong2 wv = wp[q];
                        fma2(acc2[q*2],   xd, wv.x);
                        fma2(acc2[q*2+1], xd, wv.y);
                    }
                }
            }
        }
    }
    int w = w0 + lane, h = h0 + wid;
    if (w < W_) {
        #pragma unroll
        for (int q = 0; q < 4; q++) {
            float lo, hi; unpack2(acc2[q], lo, hi);
            off[((n*G_ + 2*q  )*D_ + d)*HW_ + h*W_ + w] = lo;
            off[((n*G_ + 2*q+1)*D_ + d)*HW_ + h*W_ + w] = hi;
        }
    }
}

// ---------------------------------------------------------------------------
// Deformable conv (unchanged from R2): t1 + BN1 stats
// ---------------------------------------------------------------------------
__global__ __launch_bounds__(256) void deform_conv(
    const float* __restrict__ x, const float* __restrict__ off,
    const float* __restrict__ w1)
{
    __shared__ __align__(16) float xs[8][340];
    __shared__ __align__(16) float ws[8*9*32];
    __shared__ float offt[8][340];
    __shared__ float sw0[340], sw1[340];
    __shared__ int   so0[340], so1[340];
    __shared__ float sstat[64];
    const int tid = threadIdx.x, lane = tid & 31, wid = tid >> 5;
    const int w0 = (blockIdx.x & 1) * 32, h0 = (blockIdx.x >> 1) * 8;
    const int d = blockIdx.y % D_, n = blockIdx.y / D_;
    const int co0 = blockIdx.z * 32;

    {
        const float* ob = off + ((size_t)(n*G_ + wid)*D_ + d)*HW_;
        for (int r = lane; r < 340; r += 32) {
            int hy = r/34, wx = r%34;
            int hg = h0-1+hy, wg = w0-1+wx;
            float v = 0.f;
            if (hg >= 0 && hg < H_ && wg >= 0 && wg < W_) v = ob[hg*W_ + wg];
            offt[wid][r] = v;
        }
    }
    if (tid < 64) sstat[tid] = 0.f;

    unsigned long long acc2[16];
    #pragma unroll
    for (int q = 0; q < 16; q++) acc2[q] = 0ull;
    __syncthreads();

    #pragma unroll 1
    for (int kd = 0; kd < 3; kd++) {
        const float dk = (float)(d + kd - 1);
        #pragma unroll 1
        for (int cc = 0; cc < 8; cc++) {
            for (int r = tid; r < 340; r += 256) {
                int hy = r/34, wx = r%34;
                int hg = h0-1+hy, wg = w0-1+wx;
                bool sval = (hg >= 0 && hg < H_ && wg >= 0 && wg < W_);
                float pos = offt[cc][r] + dk;
                float f0f = floorf(pos);
                float fr = pos - f0f;
                int i0 = (int)f0f;
                bool m0 = sval && (i0 >= 0) && (i0 < D_);
                bool m1 = sval && (i0+1 >= 0) && (i0+1 < D_);
                int spat = sval ? hg*W_ + wg : 0;
                so0[r] = (m0 ? i0     : 0)*HW_ + spat;
                so1[r] = (m1 ? (i0+1) : 0)*HW_ + spat;
                sw0[r] = m0 ? (1.f - fr) : 0.f;
                sw1[r] = m1 ? fr : 0.f;
            }
            for (int i = tid; i < 8*9*32; i += 256) {
                int co = i & 31, k = (i >> 5) % 9, ci = i / 288;
                ws[i] = w1[((size_t)(co0+co)*C_ + cc*8+ci)*27 + kd*9 + k];
            }
            __syncthreads();
            {
                const float* xb = x + (size_t)(n*C_ + cc*8 + wid)*DHW_;
                for (int r = lane; r < 340; r += 32)
                    xs[wid][r] = xb[so0[r]]*sw0[r] + xb[so1[r]]*sw1[r];
            }
            __syncthreads();
            #pragma unroll 2
            for (int ci = 0; ci < 8; ci++) {
                float xv[9];
                #pragma unroll
                for (int kh = 0; kh < 3; kh++)
                #pragma unroll
                for (int kw = 0; kw < 3; kw++)
                    xv[kh*3+kw] = xs[ci][(wid+kh)*34 + lane+kw];
                #pragma unroll
                for (int k = 0; k < 9; k++) {
                    unsigned long long xd = pack2(xv[k]);
                    const ulonglong2* wp = (const ulonglong2*)&ws[(ci*9 + k)*32];
                    #pragma unroll
                    for (int q = 0; q < 8; q++) {
                        ulonglong2 wv = wp[q];
                        fma2(acc2[q*2],   xd, wv.x);
                        fma2(acc2[q*2+1], xd, wv.y);
                    }
                }
            }
            __syncthreads();
        }
    }
    int w = w0 + lane, h = h0 + wid;
    bool valid = (w < W_);
    float* t1p = g_t1 + ((size_t)(n*C_ + co0)*D_ + d)*HW_ + h*W_ + w;
    #pragma unroll
    for (int q = 0; q < 16; q++) {
        float v[2]; unpack2(acc2[q], v[0], v[1]);
        #pragma unroll
        for (int u = 0; u < 2; u++) {
            int c = 2*q + u;
            float vv = valid ? v[u] : 0.f;
            if (valid) t1p[c*DHW_] = vv;
            float s = vv, sq = vv*vv;
            #pragma unroll
            for (int o = 16; o; o >>= 1) {
                s  += __shfl_xor_sync(0xffffffffu, s,  o);
                sq += __shfl_xor_sync(0xffffffffu, sq, o);
            }
            if (lane == 0) { atomicAdd(&sstat[c], s); atomicAdd(&sstat[32+c], sq); }
        }
    }
    __syncthreads();
    if (tid < 32) {
        atomicAdd(&g_sum[0][co0+tid], sstat[tid]);
        atomicAdd(&g_sum[1][co0+tid], sstat[32+tid]);
    }
}

__global__ void bn_params(const float* __restrict__ gamma,
                          const float* __restrict__ beta, int which)
{
    int c = threadIdx.x;
    if (c < C_) {
        float mean = g_sum[2*which][c] / CNT_;
        float var  = g_sum[2*which+1][c] / CNT_ - mean*mean;
        float r = rsqrtf(var + 1e-5f);
        float sc = gamma[c] * r;
        g_bn[2*which][c]   = sc;
        g_bn[2*which+1][c] = beta[c] - mean*sc;
    }
}

// ---------------------------------------------------------------------------
// u_prep: u = relu(bn1(t1)) -> NDHWC bf16 hi/lo planes
// ---------------------------------------------------------------------------
__global__ __launch_bounds__(256) void u_prep() {
    int p = blockIdx.x * 256 + threadIdx.x;    // 401408 pixels exactly
    int w = p % W_;
    int h = (p / W_) % H_;
    int dd = (p / HW_) % D_;
    int n = p / (D_*HW_);
    size_t rb = ((size_t)(n*C_)*D_ + dd)*HW_ + h*W_ + w;
    size_t wb = (size_t)p * 64;
    #pragma unroll 8
    for (int c = 0; c < 64; c += 2) {
        float v0 = g_t1[rb + (size_t)(c  )*DHW_];
        float v1 = g_t1[rb + (size_t)(c+1)*DHW_];
        float u0 = fmaxf(fmaf(g_bn[0][c],   v0, g_bn[1][c]),   0.f);
        float u1 = fmaxf(fmaf(g_bn[0][c+1], v1, g_bn[1][c+1]), 0.f);
        __nv_bfloat16 h0 = __float2bfloat16(u0), h1 = __float2bfloat16(u1);
        float r0 = u0 - __bfloat162float(h0), r1 = u1 - __bfloat162float(h1);
        *(uint32_t*)&g_uhi[wb + c] = pack_bf(h0, h1);
        *(uint32_t*)&g_ulo[wb + c] = pack_bf(__float2bfloat16(r0), __float2bfloat16(r1));
    }
}

// ---------------------------------------------------------------------------
// conv2 as implicit GEMM on tensor cores (split bf16, 3 products)
// CTA: 8 h-rows x 32 w x 64 co, 8 warps (warp = 1 h-row, 32 px)
// ---------------------------------------------------------------------------
#define US_PLANE 48960          // 340 spots * 144B
#define WB_OFF   97920          // 2 * US_PLANE
#define SMEM_SZ  (WB_OFF + 2*16384)

__global__ __launch_bounds__(256, 1) void conv2_mma() {
    extern __shared__ char sm[];
    const int tid = threadIdx.x, lane = tid & 31, wid = tid >> 5;
    const int w0 = blockIdx.x * 32;
    const int h0 = blockIdx.y * 8;
    const int d = blockIdx.z & 15, n = blockIdx.z >> 4;
    const uint32_t sbase = smem_u32(sm);

    float acc[2][8][4];
    #pragma unroll
    for (int m = 0; m < 2; m++)
    #pragma unroll
    for (int nb = 0; nb < 8; nb++)
    #pragma unroll
    for (int r = 0; r < 4; r++) acc[m][nb][r] = 0.f;

    int kds[3], nkd = 0;
    #pragma unroll
    for (int kd = 0; kd < 3; kd++) {
        int zd = d + kd - 1;
        if (zd >= 0 && zd < D_) kds[nkd++] = kd;
    }
    const int ntap = nkd * 9;

    // prefetch first tap weights
    {
        int tap = kds[0]*9;
        const char* src = (const char*)g_wb + (size_t)tap*16384 + tid*16;
        uint32_t dst = sbase + WB_OFF + tid*16;
        #pragma unroll
        for (int i = 0; i < 4; i++) cp16(dst + i*4096, src + i*4096);
        cp_commit();
    }

    const uint32_t aLaneOff = (uint32_t)(lane & 15)*144 + (uint32_t)(lane >> 4)*16;

    for (int ik = 0; ik < nkd; ik++) {
        const int kd = kds[ik];
        const int zd = d + kd - 1;
        __syncthreads();   // us free (prev kd compute done)
        // stage u planes (hi, lo) for this zd
        #pragma unroll
        for (int pl = 0; pl < 2; pl++) {
            const __nv_bfloat16* gs = pl ? g_ulo : g_uhi;
            uint32_t usb = sbase + pl*US_PLANE;
            for (int j = tid; j < 2720; j += 256) {
                int spot = j >> 3, seg = j & 7;
                int r = spot / 34, cl = spot - r*34;
                int hh = h0 - 1 + r, wg = w0 - 1 + cl;
                bool ok = (hh >= 0 && hh < H_ && wg >= 0 && wg < W_);
                int hc = ok ? hh : 0, wc = ok ? wg : 0;
                const char* src = (const char*)(gs +
                    ((((size_t)n*D_ + zd)*H_ + hc)*W_ + wc)*64 + seg*8);
                cp16z(usb + (uint32_t)spot*144 + seg*16, src, ok ? 16 : 0);
            }
        }
        cp_commit();

        for (int t9 = 0; t9 < 9; t9++) {
            const int vt = ik*9 + t9;
            const int buf = vt & 1;
            __syncthreads();   // prev tap compute done before overwriting buf^1
            if (vt + 1 < ntap) {
                int nt = kds[(vt+1)/9]*9 + (vt+1)%9;
                const char* src = (const char*)g_wb + (size_t)nt*16384 + tid*16;
                uint32_t dst = sbase + WB_OFF + ((vt+1)&1)*16384 + tid*16;
                #pragma unroll
                for (int i = 0; i < 4; i++) cp16(dst + i*4096, src + i*4096);
                cp_commit();
                cp_wait1();
            } else {
                cp_wait0();
            }
            __syncthreads();

            const int kh = t9 / 3, kw = t9 - kh*3;
            const uint32_t abase = (uint32_t)((wid + kh)*34 + kw)*144 + aLaneOff;
            const uint32_t* wptr = (const uint32_t*)(sm + WB_OFF + buf*16384);

            #pragma unroll
            for (int s = 0; s < 4; s++) {
                uint32_t ah[2][4], al[2][4];
                #pragma unroll
                for (int m = 0; m < 2; m++) {
                    uint32_t a = abase + (uint32_t)m*(16*144) + (uint32_t)s*32;
                    ldsm4(ah[m], sbase + a);
                    ldsm4(al[m], sbase + US_PLANE + a);
                }
                #pragma unroll
                for (int nb = 0; nb < 8; nb++) {
                    uint2 bh = *(const uint2*)&wptr[(s*8 + nb)*64 + lane*2];
                    uint2 bl = *(const uint2*)&wptr[2048 + (s*8 + nb)*64 + lane*2];
                    #pragma unroll
                    for (int m = 0; m < 2; m++) {
                        mma_bf16(acc[m][nb], ah[m], bh.x, bh.y);
                        mma_bf16(acc[m][nb], al[m], bh.x, bh.y);
                        mma_bf16(acc[m][nb], ah[m], bl.x, bl.y);
                    }
                }
            }
        }
    }

    // epilogue: D m16n8 -> (pixel, co)
    const int g = lane >> 2, tg = lane & 3;
    const int h = h0 + wid;
    #pragma unroll
    for (int m = 0; m < 2; m++) {
        int wA = w0 + m*16 + g;
        int wB = wA + 8;
        #pragma unroll
        for (int nb = 0; nb < 8; nb++) {
            int co = nb*8 + 2*tg;
            float* o = g_t2 + (((size_t)n*C_ + co)*D_ + d)*HW_ + h*W_;
            if (wA < W_) { o[wA] = acc[m][nb][0]; o[wA + DHW_] = acc[m][nb][1]; }
            if (wB < W_) { o[wB] = acc[m][nb][2]; o[wB + DHW_] = acc[m][nb][3]; }
        }
    }
}

// ---------------------------------------------------------------------------
// BN2 stats over g_t2
// ---------------------------------------------------------------------------
__global__ __launch_bounds__(256) void t2_reduce() {
    const int c = blockIdx.x, seg = blockIdx.y;
    const int tid = threadIdx.x, lane = tid & 31, wid = tid >> 5;
    float s = 0.f, q = 0.f;
    for (int n = 0; n < N_; n++) {
        const float4* p = (const float4*)(g_t2 + ((size_t)n*C_ + c)*DHW_);
        for (int j = tid; j < 392; j += 256) {
            float4 v = p[seg*392 + j];
            s += v.x + v.y + v.z + v.w;
            q += v.x*v.x + v.y*v.y + v.z*v.z + v.w*v.w;
        }
    }
    #pragma unroll
    for (int o = 16; o; o >>= 1) {
        s += __shfl_xor_sync(0xffffffffu, s, o);
        q += __shfl_xor_sync(0xffffffffu, q, o);
    }
    __shared__ float rs[8], rq[8];
    if (lane == 0) { rs[wid] = s; rq[wid] = q; }
    __syncthreads();
    if (tid == 0) {
        float S = 0.f, Q = 0.f;
        #pragma unroll
        for (int i = 0; i < 8; i++) { S += rs[i]; Q += rq[i]; }
        atomicAdd(&g_sum[2][c], S);
        atomicAdd(&g_sum[3][c], Q);
    }
}

__global__ void final_k(const float* __restrict__ x, float* __restrict__ out)
{
    int i4 = blockIdx.x * blockDim.x + threadIdx.x;
    if (i4 < XTOT_/4) {
        int c = (i4 / (DHW_/4)) % C_;
        float sc = g_bn[2][c], sh = g_bn[3][c];
        float4 t = ((const float4*)g_t2)[i4];
        float4 xv = ((const float4*)x)[i4];
        float4 o;
        o.x = fmaf(sc, t.x, sh) + xv.x; o.x = o.x > 0.f ? o.x : 0.f;
        o.y = fmaf(sc, t.y, sh) + xv.y; o.y = o.y > 0.f ? o.y : 0.f;
        o.z = fmaf(sc, t.z, sh) + xv.z; o.z = o.z > 0.f ? o.z : 0.f;
        o.w = fmaf(sc, t.w, sh) + xv.w; o.w = o.w > 0.f ? o.w : 0.f;
        ((float4*)out)[i4] = o;
    }
}

extern "C" void kernel_launch(void* const* d_in, const int* in_sizes, int n_in,
                              void* d_out, int out_size)
{
    const float* x     = (const float*)d_in[0];
    const float* w_off = (const float*)d_in[1];
    const float* b_off = (const float*)d_in[2];
    const float* w1    = (const float*)d_in[3];
    const float* w2    = (const float*)d_in[4];
    const float* g1    = (const float*)d_in[6];
    const float* be1   = (const float*)d_in[7];
    const float* g2    = (const float*)d_in[8];
    const float* be2   = (const float*)d_in[9];
    float* out = (float*)d_out;

    float* off_ptr;
    if (out_size >= XTOT_ + OFFTOT_) {
        off_ptr = out + XTOT_;
    } else {
        cudaGetSymbolAddress((void**)&off_ptr, g_off);
    }

    static int smem_set = 0;
    if (!smem_set) {
        cudaFuncSetAttribute(conv2_mma, cudaFuncAttributeMaxDynamicSharedMemorySize, SMEM_SZ);
        smem_set = 1;
    }

    wprep<<<108, 256>>>(w2);                             // launch 0
    offset_conv<<<dim3(14, 128), 256>>>(x, w_off, b_off, off_ptr);  // 1
    deform_conv<<<dim3(14, 128, 2), 256>>>(x, off_ptr, w1);         // 2
    bn_params<<<1, 64>>>(g1, be1, 0);                    // 3
    u_prep<<<1568, 256>>>();                             // 4
    conv2_mma<<<dim3(2, 7, 128), 256, SMEM_SZ>>>();      // 5  <- ncu -s 5
    t2_reduce<<<dim3(64, 32), 256>>>();                  // 6
    bn_params<<<1, 64>>>(g2, be2, 1);                    // 7
    final_k<<<(XTOT_/4 + 255)/256, 256>>>(x, out);       // 8
}

// round 6
// speedup vs baseline: 3.8850x; 2.4793x over previous
#include <cuda_runtime.h>
#include <cuda_bf16.h>
#include <cstdint>

#define N_ 8
#define C_ 64
#define D_ 16
#define H_ 56
#define W_ 56
#define G_ 8
#define HW_ (H_*W_)
#define DHW_ (D_*HW_)
#define XTOT_ (N_*C_*DHW_)
#define OFFTOT_ (N_*G_*DHW_)
#define CNT_ ((float)(N_*DHW_))

__device__ float g_t1[XTOT_];            // NDHWC fp32 after deform
__device__ float g_t2[XTOT_];            // NCDHW fp32 after conv2
__device__ float g_off[OFFTOT_];
__device__ float g_sum[4][C_];
__device__ float g_bn[4][C_];
__device__ __nv_bfloat16 g_uhi[XTOT_];   // NDHWC
__device__ __nv_bfloat16 g_ulo[XTOT_];
__device__ uint32_t g_wb1[27*4096];      // w1 fragments
__device__ uint32_t g_wb2[27*4096];      // w2 fragments

// ---- helpers --------------------------------------------------------------
__device__ __forceinline__ unsigned long long pack2(float x) {
    unsigned long long r;
    asm("mov.b64 %0, {%1, %1};" : "=l"(r) : "f"(x));
    return r;
}
__device__ __forceinline__ unsigned long long pack_pair(float a, float b) {
    unsigned long long r;
    asm("mov.b64 %0, {%1, %2};" : "=l"(r) : "f"(a), "f"(b));
    return r;
}
__device__ __forceinline__ void fma2(unsigned long long& d,
                                     unsigned long long a, unsigned long long b) {
    asm("fma.rn.f32x2 %0, %1, %2, %0;" : "+l"(d) : "l"(a), "l"(b));
}
__device__ __forceinline__ void unpack2(unsigned long long v, float& lo, float& hi) {
    asm("mov.b64 {%0, %1}, %2;" : "=f"(lo), "=f"(hi) : "l"(v));
}
__device__ __forceinline__ uint32_t smem_u32(const void* p) {
    uint32_t a;
    asm("{ .reg .u64 t; cvta.to.shared.u64 t, %1; cvt.u32.u64 %0, t; }" : "=r"(a) : "l"(p));
    return a;
}
__device__ __forceinline__ void cp16(uint32_t dst, const void* src) {
    asm volatile("cp.async.cg.shared.global [%0], [%1], 16;" :: "r"(dst), "l"(src) : "memory");
}
__device__ __forceinline__ void cp16z(uint32_t dst, const void* src, int sz) {
    asm volatile("cp.async.cg.shared.global [%0], [%1], 16, %2;" :: "r"(dst), "l"(src), "r"(sz) : "memory");
}
__device__ __forceinline__ void cp_commit() {
    asm volatile("cp.async.commit_group;" ::: "memory");
}
__device__ __forceinline__ void cp_wait0() {
    asm volatile("cp.async.wait_group 0;" ::: "memory");
}
__device__ __forceinline__ void cp_wait1() {
    asm volatile("cp.async.wait_group 1;" ::: "memory");
}
__device__ __forceinline__ void ldsm4(uint32_t* r, uint32_t addr) {
    asm volatile("ldmatrix.sync.aligned.m8n8.x4.shared.b16 {%0,%1,%2,%3}, [%4];"
                 : "=r"(r[0]), "=r"(r[1]), "=r"(r[2]), "=r"(r[3]) : "r"(addr));
}
__device__ __forceinline__ void mma_bf16(float* d, const uint32_t* a, uint32_t b0, uint32_t b1) {
    asm volatile("mma.sync.aligned.m16n8k16.row.col.f32.bf16.bf16.f32 "
                 "{%0,%1,%2,%3}, {%4,%5,%6,%7}, {%8,%9}, {%0,%1,%2,%3};"
                 : "+f"(d[0]), "+f"(d[1]), "+f"(d[2]), "+f"(d[3])
                 : "r"(a[0]), "r"(a[1]), "r"(a[2]), "r"(a[3]), "r"(b0), "r"(b1));
}
__device__ __forceinline__ uint32_t pack_bf(__nv_bfloat16 a, __nv_bfloat16 b) {
    return (uint32_t)__bfloat16_as_ushort(a) | ((uint32_t)__bfloat16_as_ushort(b) << 16);
}
__device__ __forceinline__ void sts128(uint32_t addr, const uint32_t* v) {
    asm volatile("st.shared.v4.b32 [%0], {%1,%2,%3,%4};"
                 :: "r"(addr), "r"(v[0]), "r"(v[1]), "r"(v[2]), "r"(v[3]) : "memory");
}

// ---------------------------------------------------------------------------
// wprep: weights -> per-lane B-fragment order (which=0 -> w1/g_wb1 + zero stats,
// which=1 -> w2/g_wb2)
// ---------------------------------------------------------------------------
__global__ void wprep(const float* __restrict__ wsrc, int which) {
    uint32_t* wdst = which ? g_wb2 : g_wb1;
    if (!which && blockIdx.x == 0 && threadIdx.x < C_) {
        g_sum[0][threadIdx.x]=0.f; g_sum[1][threadIdx.x]=0.f;
        g_sum[2][threadIdx.x]=0.f; g_sum[3][threadIdx.x]=0.f;
    }
    int t = blockIdx.x * 256 + threadIdx.x;
    if (t >= 27*4*8*32) return;
    int l = t & 31, nb = (t >> 5) & 7, s = (t >> 8) & 3, tap = t >> 10;
    int g = l >> 2, tg = l & 3;
    int co = nb*8 + g;
    int k0 = s*16 + 2*tg;
    float w00 = wsrc[(co*64 + k0    )*27 + tap];
    float w01 = wsrc[(co*64 + k0 + 1)*27 + tap];
    float w10 = wsrc[(co*64 + k0 + 8)*27 + tap];
    float w11 = wsrc[(co*64 + k0 + 9)*27 + tap];
    __nv_bfloat16 h00=__float2bfloat16(w00), h01=__float2bfloat16(w01);
    __nv_bfloat16 h10=__float2bfloat16(w10), h11=__float2bfloat16(w11);
    __nv_bfloat16 l00=__float2bfloat16(w00-__bfloat162float(h00));
    __nv_bfloat16 l01=__float2bfloat16(w01-__bfloat162float(h01));
    __nv_bfloat16 l10=__float2bfloat16(w10-__bfloat162float(h10));
    __nv_bfloat16 l11=__float2bfloat16(w11-__bfloat162float(h11));
    uint32_t base = tap*4096 + (s*8 + nb)*64 + l*2;
    wdst[base + 0]        = pack_bf(h00, h01);
    wdst[base + 1]        = pack_bf(h10, h11);
    wdst[base + 2048 + 0] = pack_bf(l00, l01);
    wdst[base + 2048 + 1] = pack_bf(l10, l11);
}

// ---------------------------------------------------------------------------
// Offset conv (validated R2 version)
// ---------------------------------------------------------------------------
__global__ __launch_bounds__(256) void offset_conv(
    const float* __restrict__ x, const float* __restrict__ wo,
    const float* __restrict__ bo, float* __restrict__ off)
{
    __shared__ __align__(16) float xs[8][340];
    __shared__ __align__(16) float ws[8*9*8];
    const int tid = threadIdx.x, lane = tid & 31, wid = tid >> 5;
    const int w0 = (blockIdx.x & 1) * 32, h0 = (blockIdx.x >> 1) * 8;
    const int d = blockIdx.y % D_, n = blockIdx.y / D_;

    unsigned long long acc2[4];
    #pragma unroll
    for (int q = 0; q < 4; q++) acc2[q] = pack_pair(bo[2*q], bo[2*q+1]);

    #pragma unroll 1
    for (int kd = 0; kd < 3; kd++) {
        int zd = d + kd - 1;
        if (zd < 0 || zd >= D_) continue;
        #pragma unroll 1
        for (int cc = 0; cc < 8; cc++) {
            __syncthreads();
            const float* xb = x + ((size_t)(n*C_ + cc*8 + wid)*D_ + zd)*HW_;
            for (int r = lane; r < 340; r += 32) {
                int hy = r/34, wx = r%34;
                int hg = h0-1+hy, wg = w0-1+wx;
                float v = 0.f;
                if (hg >= 0 && hg < H_ && wg >= 0 && wg < W_) v = xb[hg*W_ + wg];
                xs[wid][r] = v;
            }
            for (int i = tid; i < 8*9*8; i += 256) {
                int co = i & 7, k = (i >> 3) % 9, ci = i / 72;
                ws[i] = wo[(co*C_ + cc*8+ci)*27 + kd*9 + k];
            }
            __syncthreads();
            #pragma unroll 2
            for (int ci = 0; ci < 8; ci++) {
                float xv[9];
                #pragma unroll
                for (int kh = 0; kh < 3; kh++)
                #pragma unroll
                for (int kw = 0; kw < 3; kw++)
                    xv[kh*3+kw] = xs[ci][(wid+kh)*34 + lane+kw];
                #pragma unroll
                for (int k = 0; k < 9; k++) {
                    unsigned long long xd = pack2(xv[k]);
                    const ulonglong2* wp = (const ulonglong2*)&ws[(ci*9 + k)*8];
                    #pragma unroll
                    for (int q = 0; q < 2; q++) {
                        ulonglong2 wv = wp[q];
                        fma2(acc2[q*2],   xd, wv.x);
                        fma2(acc2[q*2+1], xd, wv.y);
                    }
                }
            }
        }
    }
    int w = w0 + lane, h = h0 + wid;
    if (w < W_) {
        #pragma unroll
        for (int q = 0; q < 4; q++) {
            float lo, hi; unpack2(acc2[q], lo, hi);
            off[((n*G_ + 2*q  )*D_ + d)*HW_ + h*W_ + w] = lo;
            off[((n*G_ + 2*q+1)*D_ + d)*HW_ + h*W_ + w] = hi;
        }
    }
}

// ---------------------------------------------------------------------------
// deform_mma: deformable conv on tensor cores (split bf16) + BN1 stats
// CTA: 8 h x 32 w x 64 co; A tile gathered+interp'd per kd into smem planes.
// ---------------------------------------------------------------------------
#define US_PLANE 48960          // 340 spots * 144B
#define WB_OFF   97920
#define DM_OFFT  (WB_OFF + 32768)        // 130688
#define DM_SMEM  (DM_OFFT + 8*340*4)     // 141568

__global__ __launch_bounds__(256, 1) void deform_mma(
    const float* __restrict__ x, const float* __restrict__ off)
{
    extern __shared__ char sm[];
    __shared__ float sstat[128];
    const int tid = threadIdx.x, lane = tid & 31, wid = tid >> 5;
    const int w0 = blockIdx.x * 32, h0 = blockIdx.y * 8;
    const int d = blockIdx.z & 15, n = blockIdx.z >> 4;
    const uint32_t sbase = smem_u32(sm);
    float* offt = (float*)(sm + DM_OFFT);

    // offsets tile: warp wid loads group wid
    {
        const float* ob = off + ((size_t)(n*G_ + wid)*D_ + d)*HW_;
        for (int r = lane; r < 340; r += 32) {
            int hy = r/34, wx = r%34;
            int hg = h0-1+hy, wg = w0-1+wx;
            float v = 0.f;
            if (hg >= 0 && hg < H_ && wg >= 0 && wg < W_) v = ob[hg*W_ + wg];
            offt[wid*340 + r] = v;
        }
    }
    if (tid < 128) sstat[tid] = 0.f;

    float acc[2][8][4];
    #pragma unroll
    for (int m = 0; m < 2; m++)
    #pragma unroll
    for (int nb = 0; nb < 8; nb++)
    #pragma unroll
    for (int r = 0; r < 4; r++) acc[m][nb][r] = 0.f;

    // prefetch tap 0 weights
    {
        const char* src = (const char*)g_wb1 + tid*16;
        uint32_t dst = sbase + WB_OFF + tid*16;
        #pragma unroll
        for (int i = 0; i < 4; i++) cp16(dst + i*4096, src + i*4096);
        cp_commit();
    }
    __syncthreads();   // offt + sstat visible

    const uint32_t aLaneOff = (uint32_t)(lane & 15)*144 + (uint32_t)(lane >> 4)*16;

    for (int kd = 0; kd < 3; kd++) {
        const float dk = (float)(d + kd - 1);
        __syncthreads();   // previous kd's ldsm reads done
        // gather + interp + bf16 split into A planes
        for (int j = tid; j < 2720; j += 256) {
            int seg = j / 340, spot = j - seg*340;
            int r = spot/34, cl = spot - r*34;
            int hh = h0-1+r, wg = w0-1+cl;
            bool ok = (hh >= 0 && hh < H_ && wg >= 0 && wg < W_);
            float pos = offt[seg*340 + spot] + dk;
            float f0 = floorf(pos);
            float fr = pos - f0;
            int i0 = (int)f0;
            bool m0 = ok && (i0 >= 0) && (i0 < D_);
            bool m1 = ok && (i0+1 >= 0) && (i0+1 < D_);
            int spat = ok ? hh*W_ + wg : 0;
            int o0 = (m0 ? i0     : 0)*HW_ + spat;
            int o1 = (m1 ? (i0+1) : 0)*HW_ + spat;
            float a0 = m0 ? (1.f - fr) : 0.f;
            float a1 = m1 ? fr : 0.f;
            const float* xb = x + (size_t)(n*C_ + seg*8)*DHW_;
            uint32_t hi[4], lo[4];
            #pragma unroll
            for (int cp = 0; cp < 4; cp++) {
                const float* xc = xb + (size_t)(2*cp)*DHW_;
                float v0 = xc[o0]*a0 + xc[o1]*a1;
                float v1 = xc[DHW_ + o0]*a0 + xc[DHW_ + o1]*a1;
                __nv_bfloat16 hb0 = __float2bfloat16(v0), hb1 = __float2bfloat16(v1);
                hi[cp] = pack_bf(hb0, hb1);
                lo[cp] = pack_bf(__float2bfloat16(v0 - __bfloat162float(hb0)),
                                 __float2bfloat16(v1 - __bfloat162float(hb1)));
            }
            uint32_t a = sbase + (uint32_t)spot*144 + (uint32_t)seg*16;
            sts128(a, hi);
            sts128(a + US_PLANE, lo);
        }

        for (int t9 = 0; t9 < 9; t9++) {
            const int vt = kd*9 + t9;
            const int buf = vt & 1;
            __syncthreads();   // prev tap compute done; gather STS visible
            if (vt + 1 < 27) {
                const char* src = (const char*)g_wb1 + (size_t)(vt+1)*16384 + tid*16;
                uint32_t dst = sbase + WB_OFF + ((vt+1)&1)*16384 + tid*16;
                #pragma unroll
                for (int i = 0; i < 4; i++) cp16(dst + i*4096, src + i*4096);
                cp_commit();
                cp_wait1();
            } else {
                cp_wait0();
            }
            __syncthreads();

            const int kh = t9 / 3, kw = t9 - kh*3;
            const uint32_t abase = (uint32_t)((wid + kh)*34 + kw)*144 + aLaneOff;
            const uint32_t* wptr = (const uint32_t*)(sm + WB_OFF + buf*16384);

            #pragma unroll
            for (int s = 0; s < 4; s++) {
                uint32_t ah[2][4], al[2][4];
                #pragma unroll
                for (int m = 0; m < 2; m++) {
                    uint32_t a = abase + (uint32_t)m*(16*144) + (uint32_t)s*32;
                    ldsm4(ah[m], sbase + a);
                    ldsm4(al[m], sbase + US_PLANE + a);
                }
                #pragma unroll
                for (int nb = 0; nb < 8; nb++) {
                    uint2 bh = *(const uint2*)&wptr[(s*8 + nb)*64 + lane*2];
                    uint2 bl = *(const uint2*)&wptr[2048 + (s*8 + nb)*64 + lane*2];
                    #pragma unroll
                    for (int m = 0; m < 2; m++) {
                        mma_bf16(acc[m][nb], ah[m], bh.x, bh.y);
                        mma_bf16(acc[m][nb], al[m], bh.x, bh.y);
                        mma_bf16(acc[m][nb], ah[m], bl.x, bl.y);
                    }
                }
            }
        }
    }

    // epilogue: t1 in NDHWC + BN1 stats
    const int g = lane >> 2, tg = lane & 3;
    const int h = h0 + wid;
    float* orow = g_t1 + (((size_t)n*D_ + d)*H_ + h)*W_*64;
    #pragma unroll
    for (int nb = 0; nb < 8; nb++) {
        int co = nb*8 + 2*tg;
        float s0=0.f, q0=0.f, s1=0.f, q1=0.f;
        #pragma unroll
        for (int m = 0; m < 2; m++) {
            int wA = w0 + m*16 + g, wB = wA + 8;
            if (wA < W_) {
                *(float2*)&orow[(size_t)wA*64 + co] = make_float2(acc[m][nb][0], acc[m][nb][1]);
                s0 += acc[m][nb][0]; q0 += acc[m][nb][0]*acc[m][nb][0];
                s1 += acc[m][nb][1]; q1 += acc[m][nb][1]*acc[m][nb][1];
            }
            if (wB < W_) {
                *(float2*)&orow[(size_t)wB*64 + co] = make_float2(acc[m][nb][2], acc[m][nb][3]);
                s0 += acc[m][nb][2]; q0 += acc[m][nb][2]*acc[m][nb][2];
                s1 += acc[m][nb][3]; q1 += acc[m][nb][3]*acc[m][nb][3];
            }
        }
        #pragma unroll
        for (int o = 4; o < 32; o <<= 1) {
            s0 += __shfl_xor_sync(0xffffffffu, s0, o);
            q0 += __shfl_xor_sync(0xffffffffu, q0, o);
            s1 += __shfl_xor_sync(0xffffffffu, s1, o);
            q1 += __shfl_xor_sync(0xffffffffu, q1, o);
        }
        if (lane < 4) {
            atomicAdd(&sstat[co],      s0); atomicAdd(&sstat[64+co],   q0);
            atomicAdd(&sstat[co+1],    s1); atomicAdd(&sstat[64+co+1], q1);
        }
    }
    __syncthreads();
    if (tid < 64) {
        atomicAdd(&g_sum[0][tid], sstat[tid]);
        atomicAdd(&g_sum[1][tid], sstat[64+tid]);
    }
}

__global__ void bn_params(const float* __restrict__ gamma,
                          const float* __restrict__ beta, int which)
{
    int c = threadIdx.x;
    if (c < C_) {
        float mean = g_sum[2*which][c] / CNT_;
        float var  = g_sum[2*which+1][c] / CNT_ - mean*mean;
        float r = rsqrtf(var + 1e-5f);
        float sc = gamma[c] * r;
        g_bn[2*which][c]   = sc;
        g_bn[2*which+1][c] = beta[c] - mean*sc;
    }
}

// ---------------------------------------------------------------------------
// u_prep: u = relu(bn1(t1)) -> NDHWC bf16 hi/lo (t1 already NDHWC, coalesced)
// ---------------------------------------------------------------------------
__global__ __launch_bounds__(256) void u_prep() {
    int j = blockIdx.x * 256 + threadIdx.x;       // XTOT_/2 exactly
    float2 t = ((const float2*)g_t1)[j];
    int c = (j & 31) * 2;
    float u0 = fmaxf(fmaf(g_bn[0][c],   t.x, g_bn[1][c]),   0.f);
    float u1 = fmaxf(fmaf(g_bn[0][c+1], t.y, g_bn[1][c+1]), 0.f);
    __nv_bfloat16 h0 = __float2bfloat16(u0), h1 = __float2bfloat16(u1);
    float r0 = u0 - __bfloat162float(h0), r1 = u1 - __bfloat162float(h1);
    ((uint32_t*)g_uhi)[j] = pack_bf(h0, h1);
    ((uint32_t*)g_ulo)[j] = pack_bf(__float2bfloat16(r0), __float2bfloat16(r1));
}

// ---------------------------------------------------------------------------
// conv2 on tensor cores (validated R4 version, weights from g_wb2)
// ---------------------------------------------------------------------------
#define C2_SMEM  (WB_OFF + 2*16384)

__global__ __launch_bounds__(256, 1) void conv2_mma() {
    extern __shared__ char sm[];
    const int tid = threadIdx.x, lane = tid & 31, wid = tid >> 5;
    const int w0 = blockIdx.x * 32;
    const int h0 = blockIdx.y * 8;
    const int d = blockIdx.z & 15, n = blockIdx.z >> 4;
    const uint32_t sbase = smem_u32(sm);

    float acc[2][8][4];
    #pragma unroll
    for (int m = 0; m < 2; m++)
    #pragma unroll
    for (int nb = 0; nb < 8; nb++)
    #pragma unroll
    for (int r = 0; r < 4; r++) acc[m][nb][r] = 0.f;

    int kds[3], nkd = 0;
    #pragma unroll
    for (int kd = 0; kd < 3; kd++) {
        int zd = d + kd - 1;
        if (zd >= 0 && zd < D_) kds[nkd++] = kd;
    }
    const int ntap = nkd * 9;

    {
        int tap = kds[0]*9;
        const char* src = (const char*)g_wb2 + (size_t)tap*16384 + tid*16;
        uint32_t dst = sbase + WB_OFF + tid*16;
        #pragma unroll
        for (int i = 0; i < 4; i++) cp16(dst + i*4096, src + i*4096);
        cp_commit();
    }

    const uint32_t aLaneOff = (uint32_t)(lane & 15)*144 + (uint32_t)(lane >> 4)*16;

    for (int ik = 0; ik < nkd; ik++) {
        const int kd = kds[ik];
        const int zd = d + kd - 1;
        __syncthreads();
        #pragma unroll
        for (int pl = 0; pl < 2; pl++) {
            const __nv_bfloat16* gs = pl ? g_ulo : g_uhi;
            uint32_t usb = sbase + pl*US_PLANE;
            for (int j = tid; j < 2720; j += 256) {
                int spot = j >> 3, seg = j & 7;
                int r = spot / 34, cl = spot - r*34;
                int hh = h0 - 1 + r, wg = w0 - 1 + cl;
                bool ok = (hh >= 0 && hh < H_ && wg >= 0 && wg < W_);
                int hc = ok ? hh : 0, wc = ok ? wg : 0;
                const char* src = (const char*)(gs +
                    ((((size_t)n*D_ + zd)*H_ + hc)*W_ + wc)*64 + seg*8);
                cp16z(usb + (uint32_t)spot*144 + seg*16, src, ok ? 16 : 0);
            }
        }
        cp_commit();

        for (int t9 = 0; t9 < 9; t9++) {
            const int vt = ik*9 + t9;
            const int buf = vt & 1;
            __syncthreads();
            if (vt + 1 < ntap) {
                int nt = kds[(vt+1)/9]*9 + (vt+1)%9;
                const char* src = (const char*)g_wb2 + (size_t)nt*16384 + tid*16;
                uint32_t dst = sbase + WB_OFF + ((vt+1)&1)*16384 + tid*16;
                #pragma unroll
                for (int i = 0; i < 4; i++) cp16(dst + i*4096, src + i*4096);
                cp_commit();
                cp_wait1();
            } else {
                cp_wait0();
            }
            __syncthreads();

            const int kh = t9 / 3, kw = t9 - kh*3;
            const uint32_t abase = (uint32_t)((wid + kh)*34 + kw)*144 + aLaneOff;
            const uint32_t* wptr = (const uint32_t*)(sm + WB_OFF + buf*16384);

            #pragma unroll
            for (int s = 0; s < 4; s++) {
                uint32_t ah[2][4], al[2][4];
                #pragma unroll
                for (int m = 0; m < 2; m++) {
                    uint32_t a = abase + (uint32_t)m*(16*144) + (uint32_t)s*32;
                    ldsm4(ah[m], sbase + a);
                    ldsm4(al[m], sbase + US_PLANE + a);
                }
                #pragma unroll
                for (int nb = 0; nb < 8; nb++) {
                    uint2 bh = *(const uint2*)&wptr[(s*8 + nb)*64 + lane*2];
                    uint2 bl = *(const uint2*)&wptr[2048 + (s*8 + nb)*64 + lane*2];
                    #pragma unroll
                    for (int m = 0; m < 2; m++) {
                        mma_bf16(acc[m][nb], ah[m], bh.x, bh.y);
                        mma_bf16(acc[m][nb], al[m], bh.x, bh.y);
                        mma_bf16(acc[m][nb], ah[m], bl.x, bl.y);
                    }
                }
            }
        }
    }

    const int g = lane >> 2, tg = lane & 3;
    const int h = h0 + wid;
    #pragma unroll
    for (int m = 0; m < 2; m++) {
        int wA = w0 + m*16 + g;
        int wB = wA + 8;
        #pragma unroll
        for (int nb = 0; nb < 8; nb++) {
            int co = nb*8 + 2*tg;
            float* o = g_t2 + (((size_t)n*C_ + co)*D_ + d)*HW_ + h*W_;
            if (wA < W_) { o[wA] = acc[m][nb][0]; o[wA + DHW_] = acc[m][nb][1]; }
            if (wB < W_) { o[wB] = acc[m][nb][2]; o[wB + DHW_] = acc[m][nb][3]; }
        }
    }
}

// ---------------------------------------------------------------------------
// BN2 stats over g_t2
// ---------------------------------------------------------------------------
__global__ __launch_bounds__(256) void t2_reduce() {
    const int c = blockIdx.x, seg = blockIdx.y;
    const int tid = threadIdx.x, lane = tid & 31, wid = tid >> 5;
    float s = 0.f, q = 0.f;
    for (int n = 0; n < N_; n++) {
        const float4* p = (const float4*)(g_t2 + ((size_t)n*C_ + c)*DHW_);
        for (int j = tid; j < 392; j += 256) {
            float4 v = p[seg*392 + j];
            s += v.x + v.y + v.z + v.w;
            q += v.x*v.x + v.y*v.y + v.z*v.z + v.w*v.w;
        }
    }
    #pragma unroll
    for (int o = 16; o; o >>= 1) {
        s += __shfl_xor_sync(0xffffffffu, s, o);
        q += __shfl_xor_sync(0xffffffffu, q, o);
    }
    __shared__ float rs[8], rq[8];
    if (lane == 0) { rs[wid] = s; rq[wid] = q; }
    __syncthreads();
    if (tid == 0) {
        float S = 0.f, Q = 0.f;
        #pragma unroll
        for (int i = 0; i < 8; i++) { S += rs[i]; Q += rq[i]; }
        atomicAdd(&g_sum[2][c], S);
        atomicAdd(&g_sum[3][c], Q);
    }
}

__global__ void final_k(const float* __restrict__ x, float* __restrict__ out)
{
    int i4 = blockIdx.x * blockDim.x + threadIdx.x;
    if (i4 < XTOT_/4) {
        int c = (i4 / (DHW_/4)) % C_;
        float sc = g_bn[2][c], sh = g_bn[3][c];
        float4 t = ((const float4*)g_t2)[i4];
        float4 xv = ((const float4*)x)[i4];
        float4 o;
        o.x = fmaf(sc, t.x, sh) + xv.x; o.x = o.x > 0.f ? o.x : 0.f;
        o.y = fmaf(sc, t.y, sh) + xv.y; o.y = o.y > 0.f ? o.y : 0.f;
        o.z = fmaf(sc, t.z, sh) + xv.z; o.z = o.z > 0.f ? o.z : 0.f;
        o.w = fmaf(sc, t.w, sh) + xv.w; o.w = o.w > 0.f ? o.w : 0.f;
        ((float4*)out)[i4] = o;
    }
}

extern "C" void kernel_launch(void* const* d_in, const int* in_sizes, int n_in,
                              void* d_out, int out_size)
{
    const float* x     = (const float*)d_in[0];
    const float* w_off = (const float*)d_in[1];
    const float* b_off = (const float*)d_in[2];
    const float* w1    = (const float*)d_in[3];
    const float* w2    = (const float*)d_in[4];
    const float* g1    = (const float*)d_in[6];
    const float* be1   = (const float*)d_in[7];
    const float* g2    = (const float*)d_in[8];
    const float* be2   = (const float*)d_in[9];
    float* out = (float*)d_out;

    float* off_ptr;
    if (out_size >= XTOT_ + OFFTOT_) {
        off_ptr = out + XTOT_;
    } else {
        cudaGetSymbolAddress((void**)&off_ptr, g_off);
    }

    static int smem_set = 0;
    if (!smem_set) {
        cudaFuncSetAttribute(conv2_mma,  cudaFuncAttributeMaxDynamicSharedMemorySize, C2_SMEM);
        cudaFuncSetAttribute(deform_mma, cudaFuncAttributeMaxDynamicSharedMemorySize, DM_SMEM);
        smem_set = 1;
    }

    wprep<<<108, 256>>>(w1, 0);
    wprep<<<108, 256>>>(w2, 1);
    offset_conv<<<dim3(14, 128), 256>>>(x, w_off, b_off, off_ptr);
    deform_mma<<<dim3(2, 7, 128), 256, DM_SMEM>>>(x, off_ptr);
    bn_params<<<1, 64>>>(g1, be1, 0);
    u_prep<<<XTOT_/2/256, 256>>>();
    conv2_mma<<<dim3(2, 7, 128), 256, C2_SMEM>>>();
    t2_reduce<<<dim3(64, 32), 256>>>();
    bn_params<<<1, 64>>>(g2, be2, 1);
    final_k<<<(XTOT_/4 + 255)/256, 256>>>(x, out);
}

// round 8
// speedup vs baseline: 4.0008x; 1.0298x over previous
#include <cuda_runtime.h>
#include <cuda_bf16.h>
#include <cstdint>

#define N_ 8
#define C_ 64
#define D_ 16
#define H_ 56
#define W_ 56
#define G_ 8
#define HW_ (H_*W_)
#define DHW_ (D_*HW_)
#define XTOT_ (N_*C_*DHW_)
#define OFFTOT_ (N_*G_*DHW_)
#define CNT_ ((float)(N_*DHW_))

__device__ float g_t1[XTOT_];            // NDHWC fp32 after deform
__device__ float g_t2[XTOT_];            // NCDHW fp32 after conv2
__device__ float g_off[OFFTOT_];
__device__ float g_sum[4][C_];
__device__ float g_bn[4][C_];
__device__ __nv_bfloat16 g_uhi[XTOT_];   // NDHWC
__device__ __nv_bfloat16 g_ulo[XTOT_];
__device__ uint32_t g_wb1[27*4096];      // w1 fragments
__device__ uint32_t g_wb2[27*4096];      // w2 fragments

// ---- helpers --------------------------------------------------------------
__device__ __forceinline__ unsigned long long pack2(float x) {
    unsigned long long r;
    asm("mov.b64 %0, {%1, %1};" : "=l"(r) : "f"(x));
    return r;
}
__device__ __forceinline__ unsigned long long pack_pair(float a, float b) {
    unsigned long long r;
    asm("mov.b64 %0, {%1, %2};" : "=l"(r) : "f"(a), "f"(b));
    return r;
}
__device__ __forceinline__ void fma2(unsigned long long& d,
                                     unsigned long long a, unsigned long long b) {
    asm("fma.rn.f32x2 %0, %1, %2, %0;" : "+l"(d) : "l"(a), "l"(b));
}
__device__ __forceinline__ void unpack2(unsigned long long v, float& lo, float& hi) {
    asm("mov.b64 {%0, %1}, %2;" : "=f"(lo), "=f"(hi) : "l"(v));
}
__device__ __forceinline__ uint32_t smem_u32(const void* p) {
    uint32_t a;
    asm("{ .reg .u64 t; cvta.to.shared.u64 t, %1; cvt.u32.u64 %0, t; }" : "=r"(a) : "l"(p));
    return a;
}
__device__ __forceinline__ void cp16(uint32_t dst, const void* src) {
    asm volatile("cp.async.cg.shared.global [%0], [%1], 16;" :: "r"(dst), "l"(src) : "memory");
}
__device__ __forceinline__ void cp16z(uint32_t dst, const void* src, int sz) {
    asm volatile("cp.async.cg.shared.global [%0], [%1], 16, %2;" :: "r"(dst), "l"(src), "r"(sz) : "memory");
}
__device__ __forceinline__ void cp_commit() {
    asm volatile("cp.async.commit_group;" ::: "memory");
}
__device__ __forceinline__ void cp_wait0() {
    asm volatile("cp.async.wait_group 0;" ::: "memory");
}
__device__ __forceinline__ void cp_wait1() {
    asm volatile("cp.async.wait_group 1;" ::: "memory");
}
__device__ __forceinline__ void ldsm4(uint32_t* r, uint32_t addr) {
    asm volatile("ldmatrix.sync.aligned.m8n8.x4.shared.b16 {%0,%1,%2,%3}, [%4];"
                 : "=r"(r[0]), "=r"(r[1]), "=r"(r[2]), "=r"(r[3]) : "r"(addr));
}
__device__ __forceinline__ void mma_bf16(float* d, const uint32_t* a, uint32_t b0, uint32_t b1) {
    asm volatile("mma.sync.aligned.m16n8k16.row.col.f32.bf16.bf16.f32 "
                 "{%0,%1,%2,%3}, {%4,%5,%6,%7}, {%8,%9}, {%0,%1,%2,%3};"
                 : "+f"(d[0]), "+f"(d[1]), "+f"(d[2]), "+f"(d[3])
                 : "r"(a[0]), "r"(a[1]), "r"(a[2]), "r"(a[3]), "r"(b0), "r"(b1));
}
__device__ __forceinline__ uint32_t pack_bf(__nv_bfloat16 a, __nv_bfloat16 b) {
    return (uint32_t)__bfloat16_as_ushort(a) | ((uint32_t)__bfloat16_as_ushort(b) << 16);
}
__device__ __forceinline__ void sts128(uint32_t addr, const uint32_t* v) {
    asm volatile("st.shared.v4.b32 [%0], {%1,%2,%3,%4};"
                 :: "r"(addr), "r"(v[0]), "r"(v[1]), "r"(v[2]), "r"(v[3]) : "memory");
}

// ---------------------------------------------------------------------------
// wprep: weights -> per-lane B-fragment order
// ---------------------------------------------------------------------------
__global__ void wprep(const float* __restrict__ wsrc, int which) {
    uint32_t* wdst = which ? g_wb2 : g_wb1;
    if (!which && blockIdx.x == 0 && threadIdx.x < C_) {
        g_sum[0][threadIdx.x]=0.f; g_sum[1][threadIdx.x]=0.f;
        g_sum[2][threadIdx.x]=0.f; g_sum[3][threadIdx.x]=0.f;
    }
    int t = blockIdx.x * 256 + threadIdx.x;
    if (t >= 27*4*8*32) return;
    int l = t & 31, nb = (t >> 5) & 7, s = (t >> 8) & 3, tap = t >> 10;
    int g = l >> 2, tg = l & 3;
    int co = nb*8 + g;
    int k0 = s*16 + 2*tg;
    float w00 = wsrc[(co*64 + k0    )*27 + tap];
    float w01 = wsrc[(co*64 + k0 + 1)*27 + tap];
    float w10 = wsrc[(co*64 + k0 + 8)*27 + tap];
    float w11 = wsrc[(co*64 + k0 + 9)*27 + tap];
    __nv_bfloat16 h00=__float2bfloat16(w00), h01=__float2bfloat16(w01);
    __nv_bfloat16 h10=__float2bfloat16(w10), h11=__float2bfloat16(w11);
    __nv_bfloat16 l00=__float2bfloat16(w00-__bfloat162float(h00));
    __nv_bfloat16 l01=__float2bfloat16(w01-__bfloat162float(h01));
    __nv_bfloat16 l10=__float2bfloat16(w10-__bfloat162float(h10));
    __nv_bfloat16 l11=__float2bfloat16(w11-__bfloat162float(h11));
    uint32_t base = tap*4096 + (s*8 + nb)*64 + l*2;
    wdst[base + 0]        = pack_bf(h00, h01);
    wdst[base + 1]        = pack_bf(h10, h11);
    wdst[base + 2048 + 0] = pack_bf(l00, l01);
    wdst[base + 2048 + 1] = pack_bf(l10, l11);
}

// ---------------------------------------------------------------------------
// Offset conv (validated R2 version)
// ---------------------------------------------------------------------------
__global__ __launch_bounds__(256) void offset_conv(
    const float* __restrict__ x, const float* __restrict__ wo,
    const float* __restrict__ bo, float* __restrict__ off)
{
    __shared__ __align__(16) float xs[8][340];
    __shared__ __align__(16) float ws[8*9*8];
    const int tid = threadIdx.x, lane = tid & 31, wid = tid >> 5;
    const int w0 = (blockIdx.x & 1) * 32, h0 = (blockIdx.x >> 1) * 8;
    const int d = blockIdx.y % D_, n = blockIdx.y / D_;

    unsigned long long acc2[4];
    #pragma unroll
    for (int q = 0; q < 4; q++) acc2[q] = pack_pair(bo[2*q], bo[2*q+1]);

    #pragma unroll 1
    for (int kd = 0; kd < 3; kd++) {
        int zd = d + kd - 1;
        if (zd < 0 || zd >= D_) continue;
        #pragma unroll 1
        for (int cc = 0; cc < 8; cc++) {
            __syncthreads();
            const float* xb = x + ((size_t)(n*C_ + cc*8 + wid)*D_ + zd)*HW_;
            for (int r = lane; r < 340; r += 32) {
                int hy = r/34, wx = r%34;
                int hg = h0-1+hy, wg = w0-1+wx;
                float v = 0.f;
                if (hg >= 0 && hg < H_ && wg >= 0 && wg < W_) v = xb[hg*W_ + wg];
                xs[wid][r] = v;
            }
            for (int i = tid; i < 8*9*8; i += 256) {
                int co = i & 7, k = (i >> 3) % 9, ci = i / 72;
                ws[i] = wo[(co*C_ + cc*8+ci)*27 + kd*9 + k];
            }
            __syncthreads();
            #pragma unroll 2
            for (int ci = 0; ci < 8; ci++) {
                float xv[9];
                #pragma unroll
                for (int kh = 0; kh < 3; kh++)
                #pragma unroll
                for (int kw = 0; kw < 3; kw++)
                    xv[kh*3+kw] = xs[ci][(wid+kh)*34 + lane+kw];
                #pragma unroll
                for (int k = 0; k < 9; k++) {
                    unsigned long long xd = pack2(xv[k]);
                    const ulonglong2* wp = (const ulonglong2*)&ws[(ci*9 + k)*8];
                    #pragma unroll
                    for (int q = 0; q < 2; q++) {
                        ulonglong2 wv = wp[q];
                        fma2(acc2[q*2],   xd, wv.x);
                        fma2(acc2[q*2+1], xd, wv.y);
                    }
                }
            }
        }
    }
    int w = w0 + lane, h = h0 + wid;
    if (w < W_) {
        #pragma unroll
        for (int q = 0; q < 4; q++) {
            float lo, hi; unpack2(acc2[q], lo, hi);
            off[((n*G_ + 2*q  )*D_ + d)*HW_ + h*W_ + w] = lo;
            off[((n*G_ + 2*q+1)*D_ + d)*HW_ + h*W_ + w] = hi;
        }
    }
}

// ---------------------------------------------------------------------------
// deform_mma: 8h x 16w x 64co tiles, 2 CTAs/SM for gather/MMA overlap
// ---------------------------------------------------------------------------
#define NSPOT   180            // 10 x 18 halo spots
#define US_PLANE (NSPOT*144)   // 25920
#define WB_OFF   (2*US_PLANE)  // 51840
#define DM_OFFT  (WB_OFF + 32768)        // 84608
#define DM_SMEM  (DM_OFFT + 8*NSPOT*4)   // 90368
#define C2_SMEM  (WB_OFF + 32768)        // 84608

__global__ __launch_bounds__(256, 2) void deform_mma(
    const float* __restrict__ x, const float* __restrict__ off)
{
    extern __shared__ char sm[];
    __shared__ float sstat[128];
    const int tid = threadIdx.x, lane = tid & 31, wid = tid >> 5;
    const int w0 = blockIdx.x * 16, h0 = blockIdx.y * 8;
    const int d = blockIdx.z & 15, n = blockIdx.z >> 4;
    const uint32_t sbase = smem_u32(sm);
    float* offt = (float*)(sm + DM_OFFT);

    // offsets tile: warp wid loads group wid
    {
        const float* ob = off + ((size_t)(n*G_ + wid)*D_ + d)*HW_;
        for (int r = lane; r < NSPOT; r += 32) {
            int hy = r/18, wx = r%18;
            int hg = h0-1+hy, wg = w0-1+wx;
            float v = 0.f;
            if (hg >= 0 && hg < H_ && wg >= 0 && wg < W_) v = ob[hg*W_ + wg];
            offt[wid*NSPOT + r] = v;
        }
    }
    if (tid < 128) sstat[tid] = 0.f;

    float acc[8][4];
    #pragma unroll
    for (int nb = 0; nb < 8; nb++)
    #pragma unroll
    for (int r = 0; r < 4; r++) acc[nb][r] = 0.f;

    // prefetch tap 0 weights
    {
        const char* src = (const char*)g_wb1 + tid*16;
        uint32_t dst = sbase + WB_OFF + tid*16;
        #pragma unroll
        for (int i = 0; i < 4; i++) cp16(dst + i*4096, src + i*4096);
        cp_commit();
    }
    __syncthreads();

    const uint32_t aLaneOff = (uint32_t)(lane & 15)*144 + (uint32_t)(lane >> 4)*16;

    for (int kd = 0; kd < 3; kd++) {
        const float dk = (float)(d + kd - 1);
        __syncthreads();   // previous kd's ldsm reads done
        // gather + interp + bf16 split into A planes
        for (int j = tid; j < 8*NSPOT; j += 256) {
            int seg = j / NSPOT, spot = j - seg*NSPOT;
            int r = spot/18, cl = spot - r*18;
            int hh = h0-1+r, wg = w0-1+cl;
            bool ok = (hh >= 0 && hh < H_ && wg >= 0 && wg < W_);
            float pos = offt[seg*NSPOT + spot] + dk;
            float f0 = floorf(pos);
            float fr = pos - f0;
            int i0 = (int)f0;
            bool m0 = ok && (i0 >= 0) && (i0 < D_);
            bool m1 = ok && (i0+1 >= 0) && (i0+1 < D_);
            int spat = ok ? hh*W_ + wg : 0;
            int o0 = (m0 ? i0     : 0)*HW_ + spat;
            int o1 = (m1 ? (i0+1) : 0)*HW_ + spat;
            float a0 = m0 ? (1.f - fr) : 0.f;
            float a1 = m1 ? fr : 0.f;
            const float* xb = x + (size_t)(n*C_ + seg*8)*DHW_;
            uint32_t hi[4], lo[4];
            #pragma unroll
            for (int cp = 0; cp < 4; cp++) {
                const float* xc = xb + (size_t)(2*cp)*DHW_;
                float v0 = xc[o0]*a0 + xc[o1]*a1;
                float v1 = xc[DHW_ + o0]*a0 + xc[DHW_ + o1]*a1;
                __nv_bfloat16 hb0 = __float2bfloat16(v0), hb1 = __float2bfloat16(v1);
                hi[cp] = pack_bf(hb0, hb1);
                lo[cp] = pack_bf(__float2bfloat16(v0 - __bfloat162float(hb0)),
                                 __float2bfloat16(v1 - __bfloat162float(hb1)));
            }
            uint32_t a = sbase + (uint32_t)spot*144 + (uint32_t)seg*16;
            sts128(a, hi);
            sts128(a + US_PLANE, lo);
        }

        for (int t9 = 0; t9 < 9; t9++) {
            const int vt = kd*9 + t9;
            const int buf = vt & 1;
            __syncthreads();   // prev tap compute done; gather STS visible
            if (vt + 1 < 27) {
                const char* src = (const char*)g_wb1 + (size_t)(vt+1)*16384 + tid*16;
                uint32_t dst = sbase + WB_OFF + ((vt+1)&1)*16384 + tid*16;
                #pragma unroll
                for (int i = 0; i < 4; i++) cp16(dst + i*4096, src + i*4096);
                cp_commit();
                cp_wait1();
            } else {
                cp_wait0();
            }
            __syncthreads();

            const int kh = t9 / 3, kw = t9 - kh*3;
            const uint32_t abase = (uint32_t)((wid + kh)*18 + kw)*144 + aLaneOff;
            const uint32_t* wptr = (const uint32_t*)(sm + WB_OFF + buf*16384);

            #pragma unroll
            for (int s = 0; s < 4; s++) {
                uint32_t ah[4], al[4];
                uint32_t a = abase + (uint32_t)s*32;
                ldsm4(ah, sbase + a);
                ldsm4(al, sbase + US_PLANE + a);
                #pragma unroll
                for (int nb = 0; nb < 8; nb++) {
                    uint2 bh = *(const uint2*)&wptr[(s*8 + nb)*64 + lane*2];
                    uint2 bl = *(const uint2*)&wptr[2048 + (s*8 + nb)*64 + lane*2];
                    mma_bf16(acc[nb], ah, bh.x, bh.y);
                    mma_bf16(acc[nb], al, bh.x, bh.y);
                    mma_bf16(acc[nb], ah, bl.x, bl.y);
                }
            }
        }
    }

    // epilogue: t1 in NDHWC + BN1 stats
    const int g = lane >> 2, tg = lane & 3;
    const int h = h0 + wid;
    float* orow = g_t1 + (((size_t)n*D_ + d)*H_ + h)*W_*64;
    const int wA = w0 + g, wB = wA + 8;
    #pragma unroll
    for (int nb = 0; nb < 8; nb++) {
        int co = nb*8 + 2*tg;
        float s0=0.f, q0=0.f, s1=0.f, q1=0.f;
        if (wA < W_) {
            *(float2*)&orow[(size_t)wA*64 + co] = make_float2(acc[nb][0], acc[nb][1]);
            s0 += acc[nb][0]; q0 += acc[nb][0]*acc[nb][0];
            s1 += acc[nb][1]; q1 += acc[nb][1]*acc[nb][1];
        }
        if (wB < W_) {
            *(float2*)&orow[(size_t)wB*64 + co] = make_float2(acc[nb][2], acc[nb][3]);
            s0 += acc[nb][2]; q0 += acc[nb][2]*acc[nb][2];
            s1 += acc[nb][3]; q1 += acc[nb][3]*acc[nb][3];
        }
        #pragma unroll
        for (int o = 4; o < 32; o <<= 1) {
            s0 += __shfl_xor_sync(0xffffffffu, s0, o);
            q0 += __shfl_xor_sync(0xffffffffu, q0, o);
            s1 += __shfl_xor_sync(0xffffffffu, s1, o);
            q1 += __shfl_xor_sync(0xffffffffu, q1, o);
        }
        if (lane < 4) {
            atomicAdd(&sstat[co],      s0); atomicAdd(&sstat[64+co],   q0);
            atomicAdd(&sstat[co+1],    s1); atomicAdd(&sstat[64+co+1], q1);
        }
    }
    __syncthreads();
    if (tid < 64) {
        atomicAdd(&g_sum[0][tid], sstat[tid]);
        atomicAdd(&g_sum[1][tid], sstat[64+tid]);
    }
}

__global__ void bn_params(const float* __restrict__ gamma,
                          const float* __restrict__ beta, int which)
{
    int c = threadIdx.x;
    if (c < C_) {
        float mean = g_sum[2*which][c] / CNT_;
        float var  = g_sum[2*which+1][c] / CNT_ - mean*mean;
        float r = rsqrtf(var + 1e-5f);
        float sc = gamma[c] * r;
        g_bn[2*which][c]   = sc;
        g_bn[2*which+1][c] = beta[c] - mean*sc;
    }
}

// ---------------------------------------------------------------------------
// u_prep: u = relu(bn1(t1)) -> NDHWC bf16 hi/lo
// ---------------------------------------------------------------------------
__global__ __launch_bounds__(256) void u_prep() {
    int j = blockIdx.x * 256 + threadIdx.x;       // XTOT_/2 exactly
    float2 t = ((const float2*)g_t1)[j];
    int c = (j & 31) * 2;
    float u0 = fmaxf(fmaf(g_bn[0][c],   t.x, g_bn[1][c]),   0.f);
    float u1 = fmaxf(fmaf(g_bn[0][c+1], t.y, g_bn[1][c+1]), 0.f);
    __nv_bfloat16 h0 = __float2bfloat16(u0), h1 = __float2bfloat16(u1);
    float r0 = u0 - __bfloat162float(h0), r1 = u1 - __bfloat162float(h1);
    ((uint32_t*)g_uhi)[j] = pack_bf(h0, h1);
    ((uint32_t*)g_ulo)[j] = pack_bf(__float2bfloat16(r0), __float2bfloat16(r1));
}

// ---------------------------------------------------------------------------
// conv2 on tensor cores, 8h x 16w x 64co, 2 CTAs/SM
// ---------------------------------------------------------------------------
__global__ __launch_bounds__(256, 2) void conv2_mma() {
    extern __shared__ char sm[];
    const int tid = threadIdx.x, lane = tid & 31, wid = tid >> 5;
    const int w0 = blockIdx.x * 16;
    const int h0 = blockIdx.y * 8;
    const int d = blockIdx.z & 15, n = blockIdx.z >> 4;
    const uint32_t sbase = smem_u32(sm);

    float acc[8][4];
    #pragma unroll
    for (int nb = 0; nb < 8; nb++)
    #pragma unroll
    for (int r = 0; r < 4; r++) acc[nb][r] = 0.f;

    int kds[3], nkd = 0;
    #pragma unroll
    for (int kd = 0; kd < 3; kd++) {
        int zd = d + kd - 1;
        if (zd >= 0 && zd < D_) kds[nkd++] = kd;
    }
    const int ntap = nkd * 9;

    {
        int tap = kds[0]*9;
        const char* src = (const char*)g_wb2 + (size_t)tap*16384 + tid*16;
        uint32_t dst = sbase + WB_OFF + tid*16;
        #pragma unroll
        for (int i = 0; i < 4; i++) cp16(dst + i*4096, src + i*4096);
        cp_commit();
    }

    const uint32_t aLaneOff = (uint32_t)(lane & 15)*144 + (uint32_t)(lane >> 4)*16;

    for (int ik = 0; ik < nkd; ik++) {
        const int kd = kds[ik];
        const int zd = d + kd - 1;
        __syncthreads();
        #pragma unroll
        for (int pl = 0; pl < 2; pl++) {
            const __nv_bfloat16* gs = pl ? g_ulo : g_uhi;
            uint32_t usb = sbase + pl*US_PLANE;
            for (int j = tid; j < 8*NSPOT; j += 256) {
                int spot = j >> 3, seg = j & 7;
                int r = spot / 18, cl = spot - r*18;
                int hh = h0 - 1 + r, wg = w0 - 1 + cl;
                bool ok = (hh >= 0 && hh < H_ && wg >= 0 && wg < W_);
                int hc = ok ? hh : 0, wc = ok ? wg : 0;
                const char* src = (const char*)(gs +
                    ((((size_t)n*D_ + zd)*H_ + hc)*W_ + wc)*64 + seg*8);
                cp16z(usb + (uint32_t)spot*144 + seg*16, src, ok ? 16 : 0);
            }
        }
        cp_commit();

        for (int t9 = 0; t9 < 9; t9++) {
            const int vt = ik*9 + t9;
            const int buf = vt & 1;
            __syncthreads();
            if (vt + 1 < ntap) {
                int nt = kds[(vt+1)/9]*9 + (vt+1)%9;
                const char* src = (const char*)g_wb2 + (size_t)nt*16384 + tid*16;
                uint32_t dst = sbase + WB_OFF + ((vt+1)&1)*16384 + tid*16;
                #pragma unroll
                for (int i = 0; i < 4; i++) cp16(dst + i*4096, src + i*4096);
                cp_commit();
                cp_wait1();
            } else {
                cp_wait0();
            }
            __syncthreads();

            const int kh = t9 / 3, kw = t9 - kh*3;
            const uint32_t abase = (uint32_t)((wid + kh)*18 + kw)*144 + aLaneOff;
            const uint32_t* wptr = (const uint32_t*)(sm + WB_OFF + buf*16384);

            #pragma unroll
            for (int s = 0; s < 4; s++) {
                uint32_t ah[4], al[4];
                uint32_t a = abase + (uint32_t)s*32;
                ldsm4(ah, sbase + a);
                ldsm4(al, sbase + US_PLANE + a);
                #pragma unroll
                for (int nb = 0; nb < 8; nb++) {
                    uint2 bh = *(const uint2*)&wptr[(s*8 + nb)*64 + lane*2];
                    uint2 bl = *(const uint2*)&wptr[2048 + (s*8 + nb)*64 + lane*2];
                    mma_bf16(acc[nb], ah, bh.x, bh.y);
                    mma_bf16(acc[nb], al, bh.x, bh.y);
                    mma_bf16(acc[nb], ah, bl.x, bl.y);
                }
            }
        }
    }

    const int g = lane >> 2, tg = lane & 3;
    const int h = h0 + wid;
    const int wA = w0 + g, wB = wA + 8;
    #pragma unroll
    for (int nb = 0; nb < 8; nb++) {
        int co = nb*8 + 2*tg;
        float* o = g_t2 + (((size_t)n*C_ + co)*D_ + d)*HW_ + h*W_;
        if (wA < W_) { o[wA] = acc[nb][0]; o[wA + DHW_] = acc[nb][1]; }
        if (wB < W_) { o[wB] = acc[nb][2]; o[wB + DHW_] = acc[nb][3]; }
    }
}

// ---------------------------------------------------------------------------
// BN2 stats over g_t2
// ---------------------------------------------------------------------------
__global__ __launch_bounds__(256) void t2_reduce() {
    const int c = blockIdx.x, seg = blockIdx.y;
    const int tid = threadIdx.x, lane = tid & 31, wid = tid >> 5;
    float s = 0.f, q = 0.f;
    for (int n = 0; n < N_; n++) {
        const float4* p = (const float4*)(g_t2 + ((size_t)n*C_ + c)*DHW_);
        for (int j = tid; j < 392; j += 256) {
            float4 v = p[seg*392 + j];
            s += v.x + v.y + v.z + v.w;
            q += v.x*v.x + v.y*v.y + v.z*v.z + v.w*v.w;
        }
    }
    #pragma unroll
    for (int o = 16; o; o >>= 1) {
        s += __shfl_xor_sync(0xffffffffu, s, o);
        q += __shfl_xor_sync(0xffffffffu, q, o);
    }
    __shared__ float rs[8], rq[8];
    if (lane == 0) { rs[wid] = s; rq[wid] = q; }
    __syncthreads();
    if (tid == 0) {
        float S = 0.f, Q = 0.f;
        #pragma unroll
        for (int i = 0; i < 8; i++) { S += rs[i]; Q += rq[i]; }
        atomicAdd(&g_sum[2][c], S);
        atomicAdd(&g_sum[3][c], Q);
    }
}

__global__ void final_k(const float* __restrict__ x, float* __restrict__ out)
{
    int i4 = blockIdx.x * blockDim.x + threadIdx.x;
    if (i4 < XTOT_/4) {
        int c = (i4 / (DHW_/4)) % C_;
        float sc = g_bn[2][c], sh = g_bn[3][c];
        float4 t = ((const float4*)g_t2)[i4];
        float4 xv = ((const float4*)x)[i4];
        float4 o;
        o.x = fmaf(sc, t.x, sh) + xv.x; o.x = o.x > 0.f ? o.x : 0.f;
        o.y = fmaf(sc, t.y, sh) + xv.y; o.y = o.y > 0.f ? o.y : 0.f;
        o.z = fmaf(sc, t.z, sh) + xv.z; o.z = o.z > 0.f ? o.z : 0.f;
        o.w = fmaf(sc, t.w, sh) + xv.w; o.w = o.w > 0.f ? o.w : 0.f;
        ((float4*)out)[i4] = o;
    }
}

extern "C" void kernel_launch(void* const* d_in, const int* in_sizes, int n_in,
                              void* d_out, int out_size)
{
    const float* x     = (const float*)d_in[0];
    const float* w_off = (const float*)d_in[1];
    const float* b_off = (const float*)d_in[2];
    const float* w1    = (const float*)d_in[3];
    const float* w2    = (const float*)d_in[4];
    const float* g1    = (const float*)d_in[6];
    const float* be1   = (const float*)d_in[7];
    const float* g2    = (const float*)d_in[8];
    const float* be2   = (const float*)d_in[9];
    float* out = (float*)d_out;

    float* off_ptr;
    if (out_size >= XTOT_ + OFFTOT_) {
        off_ptr = out + XTOT_;
    } else {
        cudaGetSymbolAddress((void**)&off_ptr, g_off);
    }

    static int smem_set = 0;
    if (!smem_set) {
        cudaFuncSetAttribute(conv2_mma,  cudaFuncAttributeMaxDynamicSharedMemorySize, C2_SMEM);
        cudaFuncSetAttribute(deform_mma, cudaFuncAttributeMaxDynamicSharedMemorySize, DM_SMEM);
        smem_set = 1;
    }

    wprep<<<108, 256>>>(w1, 0);
    wprep<<<108, 256>>>(w2, 1);
    offset_conv<<<dim3(14, 128), 256>>>(x, w_off, b_off, off_ptr);
    deform_mma<<<dim3(4, 7, 128), 256, DM_SMEM>>>(x, off_ptr);
    bn_params<<<1, 64>>>(g1, be1, 0);
    u_prep<<<XTOT_/2/256, 256>>>();
    conv2_mma<<<dim3(4, 7, 128), 256, C2_SMEM>>>();
    t2_reduce<<<dim3(64, 32), 256>>>();
    bn_params<<<1, 64>>>(g2, be2, 1);
    final_k<<<(XTOT_/4 + 255)/256, 256>>>(x, out);
}

// round 14
// speedup vs baseline: 4.0017x; 1.0002x over previous
#include <cuda_runtime.h>
#include <cuda_bf16.h>
#include <cstdint>

#define N_ 8
#define C_ 64
#define D_ 16
#define H_ 56
#define W_ 56
#define G_ 8
#define HW_ (H_*W_)
#define DHW_ (D_*HW_)
#define XTOT_ (N_*C_*DHW_)
#define OFFTOT_ (N_*G_*DHW_)
#define CNT_ ((float)(N_*DHW_))

__device__ float g_t1[XTOT_];            // NDHWC fp32 after deform
__device__ float g_t2[XTOT_];            // NCDHW fp32 after conv2
__device__ float g_off[OFFTOT_];
__device__ float g_sum[4][C_];
__device__ float g_bn[4][C_];
__device__ __nv_bfloat16 g_uhi[XTOT_];   // NDHWC
__device__ __nv_bfloat16 g_ulo[XTOT_];
__device__ uint32_t g_wb1[27*4096];      // w1 fragments (uint4-interleaved)
__device__ uint32_t g_wb2[27*4096];      // w2 fragments

// ---- helpers --------------------------------------------------------------
__device__ __forceinline__ unsigned long long pack2(float x) {
    unsigned long long r;
    asm("mov.b64 %0, {%1, %1};" : "=l"(r) : "f"(x));
    return r;
}
__device__ __forceinline__ unsigned long long pack_pair(float a, float b) {
    unsigned long long r;
    asm("mov.b64 %0, {%1, %2};" : "=l"(r) : "f"(a), "f"(b));
    return r;
}
__device__ __forceinline__ void fma2(unsigned long long& d,
                                     unsigned long long a, unsigned long long b) {
    asm("fma.rn.f32x2 %0, %1, %2, %0;" : "+l"(d) : "l"(a), "l"(b));
}
__device__ __forceinline__ void unpack2(unsigned long long v, float& lo, float& hi) {
    asm("mov.b64 {%0, %1}, %2;" : "=f"(lo), "=f"(hi) : "l"(v));
}
__device__ __forceinline__ uint32_t smem_u32(const void* p) {
    uint32_t a;
    asm("{ .reg .u64 t; cvta.to.shared.u64 t, %1; cvt.u32.u64 %0, t; }" : "=r"(a) : "l"(p));
    return a;
}
__device__ __forceinline__ void cp16(uint32_t dst, const void* src) {
    asm volatile("cp.async.cg.shared.global [%0], [%1], 16;" :: "r"(dst), "l"(src) : "memory");
}
__device__ __forceinline__ void cp16z(uint32_t dst, const void* src, int sz) {
    asm volatile("cp.async.cg.shared.global [%0], [%1], 16, %2;" :: "r"(dst), "l"(src), "r"(sz) : "memory");
}
__device__ __forceinline__ void cp_commit() {
    asm volatile("cp.async.commit_group;" ::: "memory");
}
__device__ __forceinline__ void cp_wait0() {
    asm volatile("cp.async.wait_group 0;" ::: "memory");
}
__device__ __forceinline__ void ldsm4(uint32_t* r, uint32_t addr) {
    asm volatile("ldmatrix.sync.aligned.m8n8.x4.shared.b16 {%0,%1,%2,%3}, [%4];"
                 : "=r"(r[0]), "=r"(r[1]), "=r"(r[2]), "=r"(r[3]) : "r"(addr));
}
__device__ __forceinline__ void mma_bf16(float* d, const uint32_t* a, uint32_t b0, uint32_t b1) {
    asm volatile("mma.sync.aligned.m16n8k16.row.col.f32.bf16.bf16.f32 "
                 "{%0,%1,%2,%3}, {%4,%5,%6,%7}, {%8,%9}, {%0,%1,%2,%3};"
                 : "+f"(d[0]), "+f"(d[1]), "+f"(d[2]), "+f"(d[3])
                 : "r"(a[0]), "r"(a[1]), "r"(a[2]), "r"(a[3]), "r"(b0), "r"(b1));
}
__device__ __forceinline__ uint32_t pack_bf(__nv_bfloat16 a, __nv_bfloat16 b) {
    return (uint32_t)__bfloat16_as_ushort(a) | ((uint32_t)__bfloat16_as_ushort(b) << 16);
}
__device__ __forceinline__ void sts128(uint32_t addr, const uint32_t* v) {
    asm volatile("st.shared.v4.b32 [%0], {%1,%2,%3,%4};"
                 :: "r"(addr), "r"(v[0]), "r"(v[1]), "r"(v[2]), "r"(v[3]) : "memory");
}

// ---------------------------------------------------------------------------
// wprep: weights -> per-lane B fragments, uint4-interleaved (bh0,bh1,bl0,bl1)
// layout: [tap][s*8+nb][lane][4] u32
// ---------------------------------------------------------------------------
__global__ void wprep(const float* __restrict__ wsrc, int which) {
    uint32_t* wdst = which ? g_wb2 : g_wb1;
    if (!which && blockIdx.x == 0 && threadIdx.x < C_) {
        g_sum[0][threadIdx.x]=0.f; g_sum[1][threadIdx.x]=0.f;
        g_sum[2][threadIdx.x]=0.f; g_sum[3][threadIdx.x]=0.f;
    }
    int t = blockIdx.x * 256 + threadIdx.x;
    if (t >= 27*4*8*32) return;
    int l = t & 31, nb = (t >> 5) & 7, s = (t >> 8) & 3, tap = t >> 10;
    int g = l >> 2, tg = l & 3;
    int co = nb*8 + g;
    int k0 = s*16 + 2*tg;
    float w00 = wsrc[(co*64 + k0    )*27 + tap];
    float w01 = wsrc[(co*64 + k0 + 1)*27 + tap];
    float w10 = wsrc[(co*64 + k0 + 8)*27 + tap];
    float w11 = wsrc[(co*64 + k0 + 9)*27 + tap];
    __nv_bfloat16 h00=__float2bfloat16(w00), h01=__float2bfloat16(w01);
    __nv_bfloat16 h10=__float2bfloat16(w10), h11=__float2bfloat16(w11);
    __nv_bfloat16 l00=__float2bfloat16(w00-__bfloat162float(h00));
    __nv_bfloat16 l01=__float2bfloat16(w01-__bfloat162float(h01));
    __nv_bfloat16 l10=__float2bfloat16(w10-__bfloat162float(h10));
    __nv_bfloat16 l11=__float2bfloat16(w11-__bfloat162float(h11));
    uint32_t base = tap*4096 + (s*8 + nb)*128 + l*4;
    wdst[base + 0] = pack_bf(h00, h01);
    wdst[base + 1] = pack_bf(h10, h11);
    wdst[base + 2] = pack_bf(l00, l01);
    wdst[base + 3] = pack_bf(l10, l11);
}

// ---------------------------------------------------------------------------
// Offset conv (validated R2 version)
// ---------------------------------------------------------------------------
__global__ __launch_bounds__(256) void offset_conv(
    const float* __restrict__ x, const float* __restrict__ wo,
    const float* __restrict__ bo, float* __restrict__ off)
{
    __shared__ __align__(16) float xs[8][340];
    __shared__ __align__(16) float ws[8*9*8];
    const int tid = threadIdx.x, lane = tid & 31, wid = tid >> 5;
    const int w0 = (blockIdx.x & 1) * 32, h0 = (blockIdx.x >> 1) * 8;
    const int d = blockIdx.y % D_, n = blockIdx.y / D_;

    unsigned long long acc2[4];
    #pragma unroll
    for (int q = 0; q < 4; q++) acc2[q] = pack_pair(bo[2*q], bo[2*q+1]);

    #pragma unroll 1
    for (int kd = 0; kd < 3; kd++) {
        int zd = d + kd - 1;
        if (zd < 0 || zd >= D_) continue;
        #pragma unroll 1
        for (int cc = 0; cc < 8; cc++) {
            __syncthreads();
            const float* xb = x + ((size_t)(n*C_ + cc*8 + wid)*D_ + zd)*HW_;
            for (int r = lane; r < 340; r += 32) {
                int hy = r/34, wx = r%34;
                int hg = h0-1+hy, wg = w0-1+wx;
                float v = 0.f;
                if (hg >= 0 && hg < H_ && wg >= 0 && wg < W_) v = xb[hg*W_ + wg];
                xs[wid][r] = v;
            }
            for (int i = tid; i < 8*9*8; i += 256) {
                int co = i & 7, k = (i >> 3) % 9, ci = i / 72;
                ws[i] = wo[(co*C_ + cc*8+ci)*27 + kd*9 + k];
            }
            __syncthreads();
            #pragma unroll 2
            for (int ci = 0; ci < 8; ci++) {
                float xv[9];
                #pragma unroll
                for (int kh = 0; kh < 3; kh++)
                #pragma unroll
                for (int kw = 0; kw < 3; kw++)
                    xv[kh*3+kw] = xs[ci][(wid+kh)*34 + lane+kw];
                #pragma unroll
                for (int k = 0; k < 9; k++) {
                    unsigned long long xd = pack2(xv[k]);
                    const ulonglong2* wp = (const ulonglong2*)&ws[(ci*9 + k)*8];
                    #pragma unroll
                    for (int q = 0; q < 2; q++) {
                        ulonglong2 wv = wp[q];
                        fma2(acc2[q*2],   xd, wv.x);
                        fma2(acc2[q*2+1], xd, wv.y);
                    }
                }
            }
        }
    }
    int w = w0 + lane, h = h0 + wid;
    if (w < W_) {
        #pragma unroll
        for (int q = 0; q < 4; q++) {
            float lo, hi; unpack2(acc2[q], lo, hi);
            off[((n*G_ + 2*q  )*D_ + d)*HW_ + h*W_ + w] = lo;
            off[((n*G_ + 2*q+1)*D_ + d)*HW_ + h*W_ + w] = hi;
        }
    }
}

// ---------------------------------------------------------------------------
// MMA conv kernels: 8h x 32w x 64co, single weight buffer, 2 CTAs/SM
// ---------------------------------------------------------------------------
#define US_PLANE 48960                  // 340 spots * 144B
#define WB_OFF   (2*US_PLANE)           // 97920
#define MM_SMEM  (WB_OFF + 16384)       // 114304

__global__ __launch_bounds__(256, 2) void deform_mma(
    const float* __restrict__ x, const float* __restrict__ off)
{
    extern __shared__ char sm[];
    __shared__ float sstat[128];
    const int tid = threadIdx.x, lane = tid & 31, wid = tid >> 5;
    const int w0 = blockIdx.x * 32, h0 = blockIdx.y * 8;
    const int d = blockIdx.z & 15, n = blockIdx.z >> 4;
    const uint32_t sbase = smem_u32(sm);

    if (tid < 128) sstat[tid] = 0.f;

    float acc[2][8][4];
    #pragma unroll
    for (int m = 0; m < 2; m++)
    #pragma unroll
    for (int nb = 0; nb < 8; nb++)
    #pragma unroll
    for (int r = 0; r < 4; r++) acc[m][nb][r] = 0.f;

    // prefetch tap 0 weights (16 KB)
    {
        const char* src = (const char*)g_wb1 + tid*16;
        uint32_t dst = sbase + WB_OFF + tid*16;
        #pragma unroll
        for (int i = 0; i < 4; i++) cp16(dst + i*4096, src + i*4096);
        cp_commit();
    }

    const uint32_t aLaneOff = (uint32_t)(lane & 15)*144 + (uint32_t)(lane >> 4)*16;

    for (int kd = 0; kd < 3; kd++) {
        const float dk = (float)(d + kd - 1);
        __syncthreads();   // previous kd's ldsm reads done (A reuse)
        // gather + interp + bf16 split into A planes (offsets straight from gmem)
        for (int j = tid; j < 2720; j += 256) {
            int seg = j / 340, spot = j - seg*340;
            int r = spot/34, cl = spot - r*34;
            int hh = h0-1+r, wg = w0-1+cl;
            bool ok = (hh >= 0 && hh < H_ && wg >= 0 && wg < W_);
            float ov = 0.f;
            if (ok) ov = off[((size_t)(n*G_ + seg)*D_ + d)*HW_ + hh*W_ + wg];
            float pos = ov + dk;
            float f0 = floorf(pos);
            float fr = pos - f0;
            int i0 = (int)f0;
            bool m0 = ok && (i0 >= 0) && (i0 < D_);
            bool m1 = ok && (i0+1 >= 0) && (i0+1 < D_);
            int spat = ok ? hh*W_ + wg : 0;
            int o0 = (m0 ? i0     : 0)*HW_ + spat;
            int o1 = (m1 ? (i0+1) : 0)*HW_ + spat;
            float a0 = m0 ? (1.f - fr) : 0.f;
            float a1 = m1 ? fr : 0.f;
            const float* xb = x + (size_t)(n*C_ + seg*8)*DHW_;
            uint32_t hi[4], lo[4];
            #pragma unroll
            for (int cp = 0; cp < 4; cp++) {
                const float* xc = xb + (size_t)(2*cp)*DHW_;
                float v0 = xc[o0]*a0 + xc[o1]*a1;
                float v1 = xc[DHW_ + o0]*a0 + xc[DHW_ + o1]*a1;
                __nv_bfloat16 hb0 = __float2bfloat16(v0), hb1 = __float2bfloat16(v1);
                hi[cp] = pack_bf(hb0, hb1);
                lo[cp] = pack_bf(__float2bfloat16(v0 - __bfloat162float(hb0)),
                                 __float2bfloat16(v1 - __bfloat162float(hb1)));
            }
            uint32_t a = sbase + (uint32_t)spot*144 + (uint32_t)seg*16;
            sts128(a, hi);
            sts128(a + US_PLANE, lo);
        }

        for (int t9 = 0; t9 < 9; t9++) {
            const int vt = kd*9 + t9;
            __syncthreads();   // prev tap mma done; gather STS visible
            if (vt) {
                const char* src = (const char*)g_wb1 + (size_t)vt*16384 + tid*16;
                uint32_t dst = sbase + WB_OFF + tid*16;
                #pragma unroll
                for (int i = 0; i < 4; i++) cp16(dst + i*4096, src + i*4096);
                cp_commit();
            }
            cp_wait0();
            __syncthreads();

            const int kh = t9 / 3, kw = t9 - kh*3;
            const uint32_t abase = (uint32_t)((wid + kh)*34 + kw)*144 + aLaneOff;
            const uint32_t* wptr = (const uint32_t*)(sm + WB_OFF);

            #pragma unroll
            for (int s = 0; s < 4; s++) {
                uint32_t ah[2][4], al[2][4];
                #pragma unroll
                for (int m = 0; m < 2; m++) {
                    uint32_t a = abase + (uint32_t)m*(16*144) + (uint32_t)s*32;
                    ldsm4(ah[m], sbase + a);
                    ldsm4(al[m], sbase + US_PLANE + a);
                }
                #pragma unroll
                for (int nb = 0; nb < 8; nb++) {
                    uint4 b = *(const uint4*)&wptr[(s*8 + nb)*128 + lane*4];
                    #pragma unroll
                    for (int m = 0; m < 2; m++) {
                        mma_bf16(acc[m][nb], ah[m], b.x, b.y);
                        mma_bf16(acc[m][nb], al[m], b.x, b.y);
                        mma_bf16(acc[m][nb], ah[m], b.z, b.w);
                    }
                }
            }
        }
    }

    // epilogue: t1 in NDHWC + BN1 stats
    const int g = lane >> 2, tg = lane & 3;
    const int h = h0 + wid;
    float* orow = g_t1 + (((size_t)n*D_ + d)*H_ + h)*W_*64;
    #pragma unroll
    for (int nb = 0; nb < 8; nb++) {
        int co = nb*8 + 2*tg;
        float s0=0.f, q0=0.f, s1=0.f, q1=0.f;
        #pragma unroll
        for (int m = 0; m < 2; m++) {
            int wA = w0 + m*16 + g, wB = wA + 8;
            if (wA < W_) {
                *(float2*)&orow[(size_t)wA*64 + co] = make_float2(acc[m][nb][0], acc[m][nb][1]);
                s0 += acc[m][nb][0]; q0 += acc[m][nb][0]*acc[m][nb][0];
                s1 += acc[m][nb][1]; q1 += acc[m][nb][1]*acc[m][nb][1];
            }
            if (wB < W_) {
                *(float2*)&orow[(size_t)wB*64 + co] = make_float2(acc[m][nb][2], acc[m][nb][3]);
                s0 += acc[m][nb][2]; q0 += acc[m][nb][2]*acc[m][nb][2];
                s1 += acc[m][nb][3]; q1 += acc[m][nb][3]*acc[m][nb][3];
            }
        }
        #pragma unroll
        for (int o = 4; o < 32; o <<= 1) {
            s0 += __shfl_xor_sync(0xffffffffu, s0, o);
            q0 += __shfl_xor_sync(0xffffffffu, q0, o);
            s1 += __shfl_xor_sync(0xffffffffu, s1, o);
            q1 += __shfl_xor_sync(0xffffffffu, q1, o);
        }
        if (lane < 4) {
            atomicAdd(&sstat[co],      s0); atomicAdd(&sstat[64+co],   q0);
            atomicAdd(&sstat[co+1],    s1); atomicAdd(&sstat[64+co+1], q1);
        }
    }
    __syncthreads();
    if (tid < 64) {
        atomicAdd(&g_sum[0][tid], sstat[tid]);
        atomicAdd(&g_sum[1][tid], sstat[64+tid]);
    }
}

__global__ void bn_params(const float* __restrict__ gamma,
                          const float* __restrict__ beta, int which)
{
    int c = threadIdx.x;
    if (c < C_) {
        float mean = g_sum[2*which][c] / CNT_;
        float var  = g_sum[2*which+1][c] / CNT_ - mean*mean;
        float r = rsqrtf(var + 1e-5f);
        float sc = gamma[c] * r;
        g_bn[2*which][c]   = sc;
        g_bn[2*which+1][c] = beta[c] - mean*sc;
    }
}

// ---------------------------------------------------------------------------
// u_prep: u = relu(bn1(t1)) -> NDHWC bf16 hi/lo
// ---------------------------------------------------------------------------
__global__ __launch_bounds__(256) void u_prep() {
    int j = blockIdx.x * 256 + threadIdx.x;       // XTOT_/2 exactly
    float2 t = ((const float2*)g_t1)[j];
    int c = (j & 31) * 2;
    float u0 = fmaxf(fmaf(g_bn[0][c],   t.x, g_bn[1][c]),   0.f);
    float u1 = fmaxf(fmaf(g_bn[0][c+1], t.y, g_bn[1][c+1]), 0.f);
    __nv_bfloat16 h0 = __float2bfloat16(u0), h1 = __float2bfloat16(u1);
    float r0 = u0 - __bfloat162float(h0), r1 = u1 - __bfloat162float(h1);
    ((uint32_t*)g_uhi)[j] = pack_bf(h0, h1);
    ((uint32_t*)g_ulo)[j] = pack_bf(__float2bfloat16(r0), __float2bfloat16(r1));
}

// ---------------------------------------------------------------------------
// conv2: 8h x 32w x 64co, single weight buffer, 2 CTAs/SM
// ---------------------------------------------------------------------------
__global__ __launch_bounds__(256, 2) void conv2_mma() {
    extern __shared__ char sm[];
    const int tid = threadIdx.x, lane = tid & 31, wid = tid >> 5;
    const int w0 = blockIdx.x * 32;
    const int h0 = blockIdx.y * 8;
    const int d = blockIdx.z & 15, n = blockIdx.z >> 4;
    const uint32_t sbase = smem_u32(sm);

    float acc[2][8][4];
    #pragma unroll
    for (int m = 0; m < 2; m++)
    #pragma unroll
    for (int nb = 0; nb < 8; nb++)
    #pragma unroll
    for (int r = 0; r < 4; r++) acc[m][nb][r] = 0.f;

    int kds[3], nkd = 0;
    #pragma unroll
    for (int kd = 0; kd < 3; kd++) {
        int zd = d + kd - 1;
        if (zd >= 0 && zd < D_) kds[nkd++] = kd;
    }

    // prefetch first tap weights
    {
        int tap = kds[0]*9;
        const char* src = (const char*)g_wb2 + (size_t)tap*16384 + tid*16;
        uint32_t dst = sbase + WB_OFF + tid*16;
        #pragma unroll
        for (int i = 0; i < 4; i++) cp16(dst + i*4096, src + i*4096);
        cp_commit();
    }

    const uint32_t aLaneOff = (uint32_t)(lane & 15)*144 + (uint32_t)(lane >> 4)*16;

    for (int ik = 0; ik < nkd; ik++) {
        const int zd = d + kds[ik] - 1;
        __syncthreads();   // A reuse guard
        #pragma unroll
        for (int pl = 0; pl < 2; pl++) {
            const __nv_bfloat16* gs = pl ? g_ulo : g_uhi;
            uint32_t usb = sbase + pl*US_PLANE;
            for (int j = tid; j < 2720; j += 256) {
                int spot = j >> 3, seg = j & 7;
                int r = spot / 34, cl = spot - r*34;
                int hh = h0 - 1 + r, wg = w0 - 1 + cl;
                bool ok = (hh >= 0 && hh < H_ && wg >= 0 && wg < W_);
                int hc = ok ? hh : 0, wc = ok ? wg : 0;
                const char* src = (const char*)(gs +
                    ((((size_t)n*D_ + zd)*H_ + hc)*W_ + wc)*64 + seg*8);
                cp16z(usb + (uint32_t)spot*144 + seg*16, src, ok ? 16 : 0);
            }
        }
        cp_commit();

        for (int t9 = 0; t9 < 9; t9++) {
            const int vt = ik*9 + t9;
            __syncthreads();   // prev tap mma done
            if (vt) {
                int nt = kds[ik]*9 + t9;
                const char* src = (const char*)g_wb2 + (size_t)nt*16384 + tid*16;
                uint32_t dst = sbase + WB_OFF + tid*16;
                #pragma unroll
                for (int i = 0; i < 4; i++) cp16(dst + i*4096, src + i*4096);
                cp_commit();
            }
            cp_wait0();        // weights (and A planes at t9==0)
            __syncthreads();

            const int kh = t9 / 3, kw = t9 - kh*3;
            const uint32_t abase = (uint32_t)((wid + kh)*34 + kw)*144 + aLaneOff;
            const uint32_t* wptr = (const uint32_t*)(sm + WB_OFF);

            #pragma unroll
            for (int s = 0; s < 4; s++) {
                uint32_t ah[2][4], al[2][4];
                #pragma unroll
                for (int m = 0; m < 2; m++) {
                    uint32_t a = abase + (uint32_t)m*(16*144) + (uint32_t)s*32;
                    ldsm4(ah[m], sbase + a);
                    ldsm4(al[m], sbase + US_PLANE + a);
                }
                #pragma unroll
                for (int nb = 0; nb < 8; nb++) {
                    uint4 b = *(const uint4*)&wptr[(s*8 + nb)*128 + lane*4];
                    #pragma unroll
                    for (int m = 0; m < 2; m++) {
                        mma_bf16(acc[m][nb], ah[m], b.x, b.y);
                        mma_bf16(acc[m][nb], al[m], b.x, b.y);
                        mma_bf16(acc[m][nb], ah[m], b.z, b.w);
                    }
                }
            }
        }
    }

    const int g = lane >> 2, tg = lane & 3;
    const int h = h0 + wid;
    #pragma unroll
    for (int m = 0; m < 2; m++) {
        int wA = w0 + m*16 + g;
        int wB = wA + 8;
        #pragma unroll
        for (int nb = 0; nb < 8; nb++) {
            int co = nb*8 + 2*tg;
            float* o = g_t2 + (((size_t)n*C_ + co)*D_ + d)*HW_ + h*W_;
            if (wA < W_) { o[wA] = acc[m][nb][0]; o[wA + DHW_] = acc[m][nb][1]; }
            if (wB < W_) { o[wB] = acc[m][nb][2]; o[wB + DHW_] = acc[m][nb][3]; }
        }
    }
}

// ---------------------------------------------------------------------------
// BN2 stats over g_t2
// ---------------------------------------------------------------------------
__global__ __launch_bounds__(256) void t2_reduce() {
    const int c = blockIdx.x, seg = blockIdx.y;
    const int tid = threadIdx.x, lane = tid & 31, wid = tid >> 5;
    float s = 0.f, q = 0.f;
    for (int n = 0; n < N_; n++) {
        const float4* p = (const float4*)(g_t2 + ((size_t)n*C_ + c)*DHW_);
        for (int j = tid; j < 392; j += 256) {
            float4 v = p[seg*392 + j];
            s += v.x + v.y + v.z + v.w;
            q += v.x*v.x + v.y*v.y + v.z*v.z + v.w*v.w;
        }
    }
    #pragma unroll
    for (int o = 16; o; o >>= 1) {
        s += __shfl_xor_sync(0xffffffffu, s, o);
        q += __shfl_xor_sync(0xffffffffu, q, o);
    }
    __shared__ float rs[8], rq[8];
    if (lane == 0) { rs[wid] = s; rq[wid] = q; }
    __syncthreads();
    if (tid == 0) {
        float S = 0.f, Q = 0.f;
        #pragma unroll
        for (int i = 0; i < 8; i++) { S += rs[i]; Q += rq[i]; }
        atomicAdd(&g_sum[2][c], S);
        atomicAdd(&g_sum[3][c], Q);
    }
}

__global__ void final_k(const float* __restrict__ x, float* __restrict__ out)
{
    int i4 = blockIdx.x * blockDim.x + threadIdx.x;
    if (i4 < XTOT_/4) {
        int c = (i4 / (DHW_/4)) % C_;
        float sc = g_bn[2][c], sh = g_bn[3][c];
        float4 t = ((const float4*)g_t2)[i4];
        float4 xv = ((const float4*)x)[i4];
        float4 o;
        o.x = fmaf(sc, t.x, sh) + xv.x; o.x = o.x > 0.f ? o.x : 0.f;
        o.y = fmaf(sc, t.y, sh) + xv.y; o.y = o.y > 0.f ? o.y : 0.f;
        o.z = fmaf(sc, t.z, sh) + xv.z; o.z = o.z > 0.f ? o.z : 0.f;
        o.w = fmaf(sc, t.w, sh) + xv.w; o.w = o.w > 0.f ? o.w : 0.f;
        ((float4*)out)[i4] = o;
    }
}

extern "C" void kernel_launch(void* const* d_in, const int* in_sizes, int n_in,
                              void* d_out, int out_size)
{
    const float* x     = (const float*)d_in[0];
    const float* w_off = (const float*)d_in[1];
    const float* b_off = (const float*)d_in[2];
    const float* w1    = (const float*)d_in[3];
    const float* w2    = (const float*)d_in[4];
    const float* g1    = (const float*)d_in[6];
    const float* be1   = (const float*)d_in[7];
    const float* g2    = (const float*)d_in[8];
    const float* be2   = (const float*)d_in[9];
    float* out = (float*)d_out;

    float* off_ptr;
    if (out_size >= XTOT_ + OFFTOT_) {
        off_ptr = out + XTOT_;
    } else {
        cudaGetSymbolAddress((void**)&off_ptr, g_off);
    }

    static int smem_set = 0;
    if (!smem_set) {
        cudaFuncSetAttribute(conv2_mma,  cudaFuncAttributeMaxDynamicSharedMemorySize, MM_SMEM);
        cudaFuncSetAttribute(deform_mma, cudaFuncAttributeMaxDynamicSharedMemorySize, MM_SMEM);
        smem_set = 1;
    }

    wprep<<<108, 256>>>(w1, 0);
    wprep<<<108, 256>>>(w2, 1);
    offset_conv<<<dim3(14, 128), 256>>>(x, w_off, b_off, off_ptr);
    deform_mma<<<dim3(2, 7, 128), 256, MM_SMEM>>>(x, off_ptr);
    bn_params<<<1, 64>>>(g1, be1, 0);
    u_prep<<<XTOT_/2/256, 256>>>();
    conv2_mma<<<dim3(2, 7, 128), 256, MM_SMEM>>>();
    t2_reduce<<<dim3(64, 32), 256>>>();
    bn_params<<<1, 64>>>(g2, be2, 1);
    final_k<<<(XTOT_/4 + 255)/256, 256>>>(x, out);
}